// round 12
// baseline (speedup 1.0000x reference)
#include <cuda_runtime.h>
#include <cuda_fp16.h>
#include <math.h>
#include <stdint.h>

// ---------------- problem constants ----------------
constexpr int kB  = 2;
constexpr int kT  = 2048;
constexpr int kD  = 1024;
constexpr int kH  = 16;
constexpr int kDH = 64;
constexpr int kFF = 4096;
constexpr int kE  = 4;
constexpr int kNT = kB * kT;           // 4096 tokens
constexpr float kEPS = 1e-5f;

// ---------------- scratch (device globals: allocation-free) ----------------
__device__ float g_proj[kNT * kD];
__device__ float g_x1[kNT * kD];
__device__ float g_y[kNT * kD];
__device__ int   g_cnt[kE];
__device__ int   g_list[kE * kNT];

// fp16 planes: A-side arrays hi only; K/V and weights hi+lo
__device__ __half g_xb_h[kNT * kD];
__device__ __half g_qb_h[kNT * kD];
__device__ __half g_kb_h[kNT * kD],  g_kb_l[kNT * kD];
__device__ __half g_vb_h[kNT * kD],  g_vb_l[kNT * kD];
__device__ __half g_ab_h[kNT * kD];
__device__ __half g_x1b_h[kNT * kD];
__device__ __half g_hb_h[(size_t)kNT * kFF];

__device__ __half g_w4t_h[4 * kD * kD], g_w4t_l[4 * kD * kD];   // Wq,Wk,Wv,Wo [N][K]
__device__ __half g_w1t_h[(size_t)kE * kFF * kD], g_w1t_l[(size_t)kE * kFF * kD];
__device__ __half g_w2t_h[(size_t)kE * kFF * kD], g_w2t_l[(size_t)kE * kFF * kD];

// ==================== PTX helpers (base sm_103 features only) ====================
__device__ __forceinline__ uint32_t smem_u32(const void* p) {
    uint32_t a;
    asm("{ .reg .u64 t; cvta.to.shared.u64 t, %1; cvt.u32.u64 %0, t; }" : "=r"(a) : "l"(p));
    return a;
}

__device__ __forceinline__ void cp_async16(uint32_t s, const void* g, int sz) {
    asm volatile("cp.async.cg.shared.global [%0], [%1], 16, %2;"
                 :: "r"(s), "l"(g), "r"(sz) : "memory");
}
#define CP_COMMIT()  asm volatile("cp.async.commit_group;" ::: "memory")
#define CP_WAIT(n)   asm volatile("cp.async.wait_group %0;" :: "n"(n) : "memory")

__device__ __forceinline__ void ldsm_x4(uint32_t& r0, uint32_t& r1, uint32_t& r2,
                                        uint32_t& r3, uint32_t addr) {
    asm volatile("ldmatrix.sync.aligned.m8n8.x4.shared.b16 {%0,%1,%2,%3}, [%4];"
                 : "=r"(r0), "=r"(r1), "=r"(r2), "=r"(r3) : "r"(addr));
}
__device__ __forceinline__ void ldsm_x4_t(uint32_t& r0, uint32_t& r1, uint32_t& r2,
                                          uint32_t& r3, uint32_t addr) {
    asm volatile("ldmatrix.sync.aligned.m8n8.x4.trans.shared.b16 {%0,%1,%2,%3}, [%4];"
                 : "=r"(r0), "=r"(r1), "=r"(r2), "=r"(r3) : "r"(addr));
}

__device__ __forceinline__ void mma16816(float* d, const uint32_t* a,
                                         uint32_t b0, uint32_t b1) {
    asm volatile("mma.sync.aligned.m16n8k16.row.col.f32.f16.f16.f32 "
                 "{%0,%1,%2,%3}, {%4,%5,%6,%7}, {%8,%9}, {%0,%1,%2,%3};"
                 : "+f"(d[0]), "+f"(d[1]), "+f"(d[2]), "+f"(d[3])
                 : "r"(a[0]), "r"(a[1]), "r"(a[2]), "r"(a[3]), "r"(b0), "r"(b1));
}

__device__ __forceinline__ uint32_t pack2h(float f0, float f1) {
    __half2 hv = __floats2half2_rn(f0, f1);
    return *reinterpret_cast<uint32_t*>(&hv);
}
__device__ __forceinline__ void split2h(float f0, float f1, uint32_t& h, uint32_t& l) {
    __half2 hv = __floats2half2_rn(f0, f1);
    float r0 = f0 - __half2float(__low2half(hv));
    float r1 = f1 - __half2float(__high2half(hv));
    __half2 lv = __floats2half2_rn(r0, r1);
    h = *reinterpret_cast<uint32_t*>(&hv);
    l = *reinterpret_cast<uint32_t*>(&lv);
}

// ==================== mma.sync 2-pass fp16 GEMM ====================
// Block 128x128, 256 threads (8 warps, 2Mx4N), warp tile 64x32, K-chunk 32.
// Planes per stage: Ah, Bh, Bl (XOR-swizzled 64B rows), 3-stage cp.async.
// Inner loop: hi pass then lo pass -> no back-to-back same-accumulator MMAs.
constexpr int kPlaneB = 128 * 64;              // 8192 B per plane
constexpr int kStageB = 3 * kPlaneB;           // Ah Bh Bl = 24576
constexpr int GEMM_SMEM = 3 * kStageB;         // 73728

__device__ __forceinline__ uint32_t swz(int row, int cb) {
    return (uint32_t)(row * 64 + ((((cb >> 4) ^ ((row >> 1) & 3))) << 4));
}

struct GemmPtrs {
    const __half *aH0, *aH1;
    const __half *bH0, *bL0, *bH1, *bL1;
    int v0, v1, c8;
};

__device__ __forceinline__ void fill_stage(uint32_t sb, int k0, const GemmPtrs& P)
{
    int row = threadIdx.x >> 2;                 // 0..63
    int cb  = (threadIdx.x & 3) * 16;
    uint32_t o0 = swz(row, cb);
    uint32_t o1 = o0 + 64 * 64;
    int g = k0 + P.c8;
    cp_async16(sb + o0,             P.aH0 + g, P.v0 ? 16 : 0);
    cp_async16(sb + o1,             P.aH1 + g, P.v1 ? 16 : 0);
    cp_async16(sb + kPlaneB + o0,   P.bH0 + g, 16);
    cp_async16(sb + kPlaneB + o1,   P.bH1 + g, 16);
    cp_async16(sb + 2*kPlaneB + o0, P.bL0 + g, 16);
    cp_async16(sb + 2*kPlaneB + o1, P.bL1 + g, 16);
}

// mode 0: C = acc + bias (fp32)
// mode 1: relu(acc+bias) -> Chi (fp16 hi only)
// mode 2: (acc+bias)*scale -> Chi (+Clo if non-null)
__device__ __forceinline__ void gemm_tc(
    const __half* __restrict__ Ah,
    const __half* __restrict__ Bh, const __half* __restrict__ Bl,
    const float* __restrict__ bias, int K, int count, const int* __restrict__ list,
    int mode, float* __restrict__ C,
    __half* __restrict__ Chi, __half* __restrict__ Clo, int ldc,
    float scale)
{
    extern __shared__ char sm[];
    const int tid  = threadIdx.x;
    const int wid  = tid >> 5, lane = tid & 31;
    const int rowBase = blockIdx.y * 128;
    const int colBase = blockIdx.x * 128;
    if (rowBase >= count) return;

    GemmPtrs P;
    {
        int r0 = tid >> 2;
        int gr0 = rowBase + r0, gr1 = rowBase + r0 + 64;
        P.v0 = gr0 < count;
        P.v1 = gr1 < count;
        int rr0 = P.v0 ? (list ? list[gr0] : gr0) : 0;
        int rr1 = P.v1 ? (list ? list[gr1] : gr1) : 0;
        P.aH0 = Ah + (size_t)rr0 * K;
        P.aH1 = Ah + (size_t)rr1 * K;
        P.bH0 = Bh + (size_t)(colBase + r0) * K;
        P.bH1 = Bh + (size_t)(colBase + r0 + 64) * K;
        P.bL0 = Bl + (size_t)(colBase + r0) * K;
        P.bL1 = Bl + (size_t)(colBase + r0 + 64) * K;
        P.c8  = (tid & 3) * 8;
    }
    const uint32_t smb = smem_u32(sm);

    // 2M x 4N warp grid: warp tile 64x32
    const int wM = (wid & 1) * 64;
    const int wN = (wid >> 1) * 32;

    float acc[4][4][4];
    #pragma unroll
    for (int i = 0; i < 4; i++)
        #pragma unroll
        for (int j = 0; j < 4; j++)
            #pragma unroll
            for (int d = 0; d < 4; d++) acc[i][j][d] = 0.f;

    const int aCol = (lane >> 4) * 16;
    const int bRow = (lane & 7) + ((lane >> 4) & 1) * 8;
    const int bCol = ((lane >> 3) & 1) * 16;
    uint32_t offA[4][2], offB[2][2];
    #pragma unroll
    for (int mi = 0; mi < 4; mi++)
        #pragma unroll
        for (int s = 0; s < 2; s++)
            offA[mi][s] = swz(wM + mi * 16 + (lane & 15), s * 32 + aCol);
    #pragma unroll
    for (int nj = 0; nj < 2; nj++)
        #pragma unroll
        for (int s = 0; s < 2; s++)
            offB[nj][s] = kPlaneB + swz(wN + nj * 16 + bRow, s * 32 + bCol);

    const int nc = K / 32;
    fill_stage(smb, 0, P);
    CP_COMMIT();
    fill_stage(smb + kStageB, 32, P);
    CP_COMMIT();

    int buf = 0;
    for (int c = 0; c < nc; c++) {
        if (c + 1 < nc) { CP_WAIT(1); } else { CP_WAIT(0); }
        __syncthreads();
        if (c + 2 < nc) {
            int nb = buf + 2; if (nb >= 3) nb -= 3;
            fill_stage(smb + nb * kStageB, (c + 2) * 32, P);
            CP_COMMIT();
        }

        uint32_t st = smb + buf * kStageB;
        #pragma unroll
        for (int s = 0; s < 2; s++) {
            uint32_t ah[4][4];
            #pragma unroll
            for (int mi = 0; mi < 4; mi++)
                ldsm_x4(ah[mi][0], ah[mi][1], ah[mi][2], ah[mi][3], st + offA[mi][s]);
            uint32_t bh[2][4], bl[2][4];
            #pragma unroll
            for (int njp = 0; njp < 2; njp++) {
                uint32_t rb = st + offB[njp][s];
                ldsm_x4(bh[njp][0], bh[njp][1], bh[njp][2], bh[njp][3], rb);
                ldsm_x4(bl[njp][0], bl[njp][1], bl[njp][2], bl[njp][3], rb + kPlaneB);
            }
            // hi pass: 16 MMAs, all distinct accumulators
            #pragma unroll
            for (int njp = 0; njp < 2; njp++)
                #pragma unroll
                for (int mi = 0; mi < 4; mi++)
                    #pragma unroll
                    for (int half = 0; half < 2; half++)
                        mma16816(acc[mi][njp * 2 + half], ah[mi],
                                 bh[njp][half * 2], bh[njp][half * 2 + 1]);
            // lo pass: 16 MMAs, all distinct accumulators
            #pragma unroll
            for (int njp = 0; njp < 2; njp++)
                #pragma unroll
                for (int mi = 0; mi < 4; mi++)
                    #pragma unroll
                    for (int half = 0; half < 2; half++)
                        mma16816(acc[mi][njp * 2 + half], ah[mi],
                                 bl[njp][half * 2], bl[njp][half * 2 + 1]);
        }
        buf = (buf < 2) ? buf + 1 : 0;
    }

    #pragma unroll
    for (int mi = 0; mi < 4; mi++) {
        #pragma unroll
        for (int dd = 0; dd < 2; dd++) {
            int lrow = rowBase + wM + mi * 16 + (lane >> 2) + dd * 8;
            if (lrow >= count) continue;
            int orow = list ? list[lrow] : lrow;
            #pragma unroll
            for (int nj = 0; nj < 4; nj++) {
                int n = colBase + wN + nj * 8 + (lane & 3) * 2;
                float v0 = acc[mi][nj][dd * 2 + 0] + bias[n];
                float v1 = acc[mi][nj][dd * 2 + 1] + bias[n + 1];
                if (mode == 0) {
                    *reinterpret_cast<float2*>(C + (size_t)orow * ldc + n)
                        = make_float2(v0, v1);
                } else {
                    if (mode == 1) { v0 = fmaxf(v0, 0.f); v1 = fmaxf(v1, 0.f); }
                    else           { v0 *= scale; v1 *= scale; }
                    size_t o = (size_t)orow * ldc + n;
                    if (Clo) {
                        uint32_t hh, ll;
                        split2h(v0, v1, hh, ll);
                        *reinterpret_cast<uint32_t*>(Chi + o) = hh;
                        *reinterpret_cast<uint32_t*>(Clo + o) = ll;
                    } else {
                        *reinterpret_cast<uint32_t*>(Chi + o) = pack2h(v0, v1);
                    }
                }
            }
        }
    }
}

// ---------------- GEMM wrappers ----------------
__global__ void __launch_bounds__(256, 2) qkv_tc(const float* bq, const float* bk, const float* bv)
{
    int z = blockIdx.z;
    const __half* bh = g_w4t_h + (size_t)z * kD * kD;
    const __half* bl = g_w4t_l + (size_t)z * kD * kD;
    __half* ch = (z == 0) ? g_qb_h : (z == 1) ? g_kb_h : g_vb_h;
    __half* cl = (z == 0) ? nullptr : (z == 1) ? g_kb_l : g_vb_l;
    const float* bias = (z == 0) ? bq : (z == 1) ? bk : bv;
    float scale = (z == 0) ? 0.125f : 1.0f;
    gemm_tc(g_xb_h, bh, bl, bias, kD, kNT, nullptr, 2, nullptr, ch, cl, kD, scale);
}

__global__ void __launch_bounds__(256, 2) proj_tc(const float* bo)
{
    gemm_tc(g_ab_h, g_w4t_h + (size_t)3 * kD * kD, g_w4t_l + (size_t)3 * kD * kD,
            bo, kD, kNT, nullptr, 0, g_proj, nullptr, nullptr, kD, 1.f);
}

__global__ void __launch_bounds__(256, 2) moe1_tc(const float* b1e)
{
    int e = blockIdx.z;
    int cnt = g_cnt[e];
    gemm_tc(g_x1b_h,
            g_w1t_h + (size_t)e * kFF * kD, g_w1t_l + (size_t)e * kFF * kD,
            b1e + (size_t)e * kFF, kD, cnt, g_list + e * kNT,
            1, nullptr, g_hb_h, nullptr, kFF, 1.f);
}

__global__ void __launch_bounds__(256, 2) moe2_tc(const float* b2e)
{
    int e = blockIdx.z;
    int cnt = g_cnt[e];
    gemm_tc(g_hb_h,
            g_w2t_h + (size_t)e * kFF * kD, g_w2t_l + (size_t)e * kFF * kD,
            b2e + (size_t)e * kD, kFF, cnt, g_list + e * kNT,
            0, g_y, nullptr, nullptr, kD, 1.f);
}

// ==================== HMMA flash attention (causal, 2-pass fp16) ====================
// Q pre-scaled by 0.125. q-tile 256 (8 warps x 32 rows), kv-tile 64.
constexpr int kARS    = 144;                   // padded row bytes
constexpr int kAPlane = 64 * kARS;             // 9216
constexpr int kAStage = 4 * kAPlane;           // Kh Kl Vh Vl = 36864
constexpr int ATTN_SMEM = 2 * kAStage;         // 73728 (Q region = stage1, 256*144)

__device__ __forceinline__ void fill_kv(uint32_t dst, int b, int h, int kbase)
{
    const __half* srcs[4] = {g_kb_h, g_kb_l, g_vb_h, g_vb_l};
    #pragma unroll
    for (int i = 0; i < 8; i++) {
        int lin = threadIdx.x + 256 * i;
        int ch = lin & 7, row = (lin >> 3) & 63, pl = lin >> 9;
        const __half* src = srcs[pl]
            + ((size_t)(b * kT + kbase + row) * kD + h * 64 + ch * 8);
        cp_async16(dst + pl * kAPlane + row * kARS + ch * 16, src, 16);
    }
}

__global__ void __launch_bounds__(256) attn_tc()
{
    extern __shared__ char sa[];
    const uint32_t smb = smem_u32(sa);
    const int tid = threadIdx.x, wid = tid >> 5, lane = tid & 31;
    const int qt = gridDim.x - 1 - blockIdx.x;   // longest-first (grid.x = 8)
    const int bh = blockIdx.y;
    const int b = bh >> 4, h = bh & 15;
    const int qb = qt * 256;
    const int wr0 = qb + wid * 32;               // warp's first q row (32 rows)

    // ---- load Q tile (256 x 64, hi only) into stage1 region (256*144 B) ----
    #pragma unroll
    for (int i = 0; i < 8; i++) {
        int lin = tid + 256 * i;
        int ch = lin & 7, row = lin >> 3;        // 0..255
        const __half* src = g_qb_h
            + ((size_t)(b * kT + qb + row) * kD + h * 64 + ch * 8);
        cp_async16(smb + kAStage + row * kARS + ch * 16, src, 16);
    }
    CP_COMMIT();
    fill_kv(smb, b, h, 0);
    CP_COMMIT();
    CP_WAIT(0);
    __syncthreads();

    // ---- Q fragments to registers: 2 m16 frags per warp ----
    uint32_t qh[4][2][4];
    #pragma unroll
    for (int ks = 0; ks < 4; ks++)
        #pragma unroll
        for (int mi = 0; mi < 2; mi++) {
            uint32_t addr = smb + kAStage
                          + (wid * 32 + mi * 16 + (lane & 15)) * kARS
                          + ks * 32 + (lane >> 4) * 16;
            ldsm_x4(qh[ks][mi][0], qh[ks][mi][1], qh[ks][mi][2], qh[ks][mi][3], addr);
        }

    float m[4] = {-1e30f, -1e30f, -1e30f, -1e30f};
    float l[4] = {0.f, 0.f, 0.f, 0.f};
    float o[2][8][4];
    #pragma unroll
    for (int mi = 0; mi < 2; mi++)
        #pragma unroll
        for (int g = 0; g < 8; g++)
            #pragma unroll
            for (int d = 0; d < 4; d++) o[mi][g][d] = 0.f;

    const int ktmax = 4 * qt + 4;
    for (int kt = 0; kt < ktmax; kt++) {
        CP_WAIT(0);
        __syncthreads();
        if (kt + 1 < ktmax) {
            fill_kv(smb + ((kt + 1) & 1) * kAStage, b, h, (kt + 1) * 64);
            CP_COMMIT();
        }

        const int kbase = kt * 64;
        if (kbase <= wr0 + 31) {
            const uint32_t st = smb + (kt & 1) * kAStage;

            // ---- S = Q K^T (2-pass), K frags shared across both Q m16 frags ----
            float s[2][8][4];
            #pragma unroll
            for (int mi = 0; mi < 2; mi++)
                #pragma unroll
                for (int j = 0; j < 8; j++)
                    #pragma unroll
                    for (int d = 0; d < 4; d++) s[mi][j][d] = 0.f;

            #pragma unroll
            for (int ks = 0; ks < 4; ks++) {
                #pragma unroll
                for (int ng = 0; ng < 4; ng++) {
                    uint32_t a = st + (ng * 16 + (lane & 7) + (lane >> 4) * 8) * kARS
                               + ks * 32 + ((lane >> 3) & 1) * 16;
                    uint32_t k0, k1, k2, k3, e0, e1, e2, e3;
                    ldsm_x4(k0, k1, k2, k3, a);
                    ldsm_x4(e0, e1, e2, e3, a + kAPlane);
                    #pragma unroll
                    for (int mi = 0; mi < 2; mi++) {
                        mma16816(s[mi][2*ng],   qh[ks][mi], k0, k1);
                        mma16816(s[mi][2*ng+1], qh[ks][mi], k2, k3);
                    }
                    #pragma unroll
                    for (int mi = 0; mi < 2; mi++) {
                        mma16816(s[mi][2*ng],   qh[ks][mi], e0, e1);
                        mma16816(s[mi][2*ng+1], qh[ks][mi], e2, e3);
                    }
                }
            }

            // ---- mask + online softmax per m16 fragment ----
            #pragma unroll
            for (int mi = 0; mi < 2; mi++) {
                const int r0 = wr0 + mi * 16 + (lane >> 2), r1 = r0 + 8;
                if (kbase + 63 > r0 - (int)(lane >> 2)) {   // straddling for this frag
                    #pragma unroll
                    for (int j = 0; j < 8; j++) {
                        int c = kbase + j * 8 + (lane & 3) * 2;
                        if (c > r0)     s[mi][j][0] = -1e30f;
                        if (c + 1 > r0) s[mi][j][1] = -1e30f;
                        if (c > r1)     s[mi][j][2] = -1e30f;
                        if (c + 1 > r1) s[mi][j][3] = -1e30f;
                    }
                }
                float rm0 = -1e30f, rm1 = -1e30f;
                #pragma unroll
                for (int j = 0; j < 8; j++) {
                    rm0 = fmaxf(rm0, fmaxf(s[mi][j][0], s[mi][j][1]));
                    rm1 = fmaxf(rm1, fmaxf(s[mi][j][2], s[mi][j][3]));
                }
                rm0 = fmaxf(rm0, __shfl_xor_sync(0xffffffffu, rm0, 1));
                rm0 = fmaxf(rm0, __shfl_xor_sync(0xffffffffu, rm0, 2));
                rm1 = fmaxf(rm1, __shfl_xor_sync(0xffffffffu, rm1, 1));
                rm1 = fmaxf(rm1, __shfl_xor_sync(0xffffffffu, rm1, 2));
                float mn0 = fmaxf(m[mi*2], rm0), mn1 = fmaxf(m[mi*2+1], rm1);
                float cr0 = __expf(m[mi*2] - mn0), cr1 = __expf(m[mi*2+1] - mn1);
                m[mi*2] = mn0; m[mi*2+1] = mn1;
                float ps0 = 0.f, ps1 = 0.f;
                #pragma unroll
                for (int j = 0; j < 8; j++) {
                    s[mi][j][0] = __expf(s[mi][j][0] - mn0);
                    s[mi][j][1] = __expf(s[mi][j][1] - mn0);
                    s[mi][j][2] = __expf(s[mi][j][2] - mn1);
                    s[mi][j][3] = __expf(s[mi][j][3] - mn1);
                    ps0 += s[mi][j][0] + s[mi][j][1];
                    ps1 += s[mi][j][2] + s[mi][j][3];
                }
                ps0 += __shfl_xor_sync(0xffffffffu, ps0, 1);
                ps0 += __shfl_xor_sync(0xffffffffu, ps0, 2);
                ps1 += __shfl_xor_sync(0xffffffffu, ps1, 1);
                ps1 += __shfl_xor_sync(0xffffffffu, ps1, 2);
                l[mi*2]   = l[mi*2]   * cr0 + ps0;
                l[mi*2+1] = l[mi*2+1] * cr1 + ps1;
                #pragma unroll
                for (int g = 0; g < 8; g++) {
                    o[mi][g][0] *= cr0; o[mi][g][1] *= cr0;
                    o[mi][g][2] *= cr1; o[mi][g][3] *= cr1;
                }
            }

            // ---- O += P V (2-pass), V frags shared across both m16 frags ----
            #pragma unroll
            for (int t = 0; t < 4; t++) {
                uint32_t ph[2][4];
                #pragma unroll
                for (int mi = 0; mi < 2; mi++) {
                    ph[mi][0] = pack2h(s[mi][2*t][0],   s[mi][2*t][1]);
                    ph[mi][1] = pack2h(s[mi][2*t][2],   s[mi][2*t][3]);
                    ph[mi][2] = pack2h(s[mi][2*t+1][0], s[mi][2*t+1][1]);
                    ph[mi][3] = pack2h(s[mi][2*t+1][2], s[mi][2*t+1][3]);
                }
                #pragma unroll
                for (int dg = 0; dg < 4; dg++) {
                    uint32_t a = st + 2 * kAPlane
                               + (t * 16 + (lane & 7) + ((lane >> 3) & 1) * 8) * kARS
                               + dg * 32 + (lane >> 4) * 16;
                    uint32_t v0, v1, v2, v3, w0, w1, w2, w3;
                    ldsm_x4_t(v0, v1, v2, v3, a);
                    ldsm_x4_t(w0, w1, w2, w3, a + kAPlane);
                    #pragma unroll
                    for (int mi = 0; mi < 2; mi++) {
                        mma16816(o[mi][2*dg],   ph[mi], v0, v1);
                        mma16816(o[mi][2*dg+1], ph[mi], v2, v3);
                    }
                    #pragma unroll
                    for (int mi = 0; mi < 2; mi++) {
                        mma16816(o[mi][2*dg],   ph[mi], w0, w1);
                        mma16816(o[mi][2*dg+1], ph[mi], w2, w3);
                    }
                }
            }
        }
    }

    // ---- epilogue: O/l -> fp16 hi plane ----
    #pragma unroll
    for (int mi = 0; mi < 2; mi++) {
        const float inv0 = 1.f / l[mi*2], inv1 = 1.f / l[mi*2+1];
        const size_t tok0 = (size_t)(b * kT) + wr0 + mi * 16 + (lane >> 2);
        #pragma unroll
        for (int g = 0; g < 8; g++) {
            int col = h * 64 + g * 8 + (lane & 3) * 2;
            *reinterpret_cast<uint32_t*>(g_ab_h + tok0 * kD + col)
                = pack2h(o[mi][g][0] * inv0, o[mi][g][1] * inv0);
            *reinterpret_cast<uint32_t*>(g_ab_h + (tok0 + 8) * kD + col)
                = pack2h(o[mi][g][2] * inv1, o[mi][g][3] * inv1);
        }
    }
}

// ---------------- conversion kernels ----------------
__global__ void convert_x(const float* __restrict__ x)
{
    int i = blockIdx.x * 256 + threadIdx.x;
    float4 v = ((const float4*)x)[i];
    size_t o = (size_t)i * 4;
    *reinterpret_cast<uint32_t*>(g_xb_h + o)     = pack2h(v.x, v.y);
    *reinterpret_cast<uint32_t*>(g_xb_h + o + 2) = pack2h(v.z, v.w);
}

__device__ __forceinline__ void transpose_body(
    const float* __restrict__ src, __half* __restrict__ hi,
    __half* __restrict__ lo, int K, int N)
{
    __shared__ float tile[32][33];
    int bn = blockIdx.x * 32, bk = blockIdx.y * 32;
    int tx = threadIdx.x, ty = threadIdx.y;
    #pragma unroll
    for (int i = 0; i < 32; i += 8)
        tile[ty + i][tx] = src[(size_t)(bk + ty + i) * N + bn + tx];
    __syncthreads();
    #pragma unroll
    for (int i = 0; i < 32; i += 8) {
        float v = tile[tx][ty + i];
        __half hh = __float2half_rn(v);
        size_t o = (size_t)(bn + ty + i) * K + bk + tx;
        hi[o] = hh;
        lo[o] = __float2half_rn(v - __half2float(hh));
    }
}

__global__ void transpose_qkvo(const float* Wq, const float* Wk, const float* Wv, const float* Wo)
{
    int z = blockIdx.z;
    const float* src = (z == 0) ? Wq : (z == 1) ? Wk : (z == 2) ? Wv : Wo;
    transpose_body(src, g_w4t_h + (size_t)z * kD * kD, g_w4t_l + (size_t)z * kD * kD, kD, kD);
}

__global__ void transpose_w1(const float* W1e)
{
    int e = blockIdx.z;
    size_t off = (size_t)e * kD * kFF;
    transpose_body(W1e + off, g_w1t_h + off, g_w1t_l + off, kD, kFF);
}

__global__ void transpose_w2(const float* W2e)
{
    int e = blockIdx.z;
    size_t off = (size_t)e * kFF * kD;
    transpose_body(W2e + off, g_w2t_h + off, g_w2t_l + off, kFF, kD);
}

// ---------------- add + layernorm ----------------
__device__ __forceinline__ float block_sum_256(float v, float* red)
{
    int tid = threadIdx.x;
    #pragma unroll
    for (int o = 16; o; o >>= 1) v += __shfl_xor_sync(0xffffffffu, v, o);
    if ((tid & 31) == 0) red[tid >> 5] = v;
    __syncthreads();
    if (tid < 8) {
        float x = red[tid];
        #pragma unroll
        for (int o = 4; o; o >>= 1) x += __shfl_xor_sync(0xffu, x, o);
        if (tid == 0) red[0] = x;
    }
    __syncthreads();
    float r = red[0];
    __syncthreads();
    return r;
}

__device__ __forceinline__ void add_ln_body(
    const float* __restrict__ A, const float* __restrict__ Bb,
    const float* __restrict__ gw, const float* __restrict__ bw,
    float* __restrict__ out, __half* __restrict__ oh)
{
    __shared__ float red[8];
    int t = blockIdx.x, tid = threadIdx.x;
    float4 av = ((const float4*)(A  + (size_t)t * kD))[tid];
    float4 bv = ((const float4*)(Bb + (size_t)t * kD))[tid];
    float vx = av.x + bv.x, vy = av.y + bv.y, vz = av.z + bv.z, vw = av.w + bv.w;
    float ssum = block_sum_256(vx + vy + vz + vw, red);
    float mu = ssum * (1.0f / kD);
    float dx = vx - mu, dy = vy - mu, dz = vz - mu, dw = vw - mu;
    float sq = block_sum_256(dx*dx + dy*dy + dz*dz + dw*dw, red);
    float rstd = rsqrtf(sq * (1.0f / kD) + kEPS);
    float4 gv = ((const float4*)gw)[tid];
    float4 be = ((const float4*)bw)[tid];
    float ovv[4] = {dx*rstd*gv.x + be.x, dy*rstd*gv.y + be.y,
                    dz*rstd*gv.z + be.z, dw*rstd*gv.w + be.w};
    ((float4*)(out + (size_t)t * kD))[tid] = make_float4(ovv[0], ovv[1], ovv[2], ovv[3]);
    if (oh) {
        size_t o = (size_t)t * kD + tid * 4;
        *reinterpret_cast<uint32_t*>(oh + o)     = pack2h(ovv[0], ovv[1]);
        *reinterpret_cast<uint32_t*>(oh + o + 2) = pack2h(ovv[2], ovv[3]);
    }
}

__global__ void ln1_kernel(const float* __restrict__ x,
                           const float* __restrict__ g, const float* __restrict__ b)
{
    add_ln_body(x, g_proj, g, b, g_x1, g_x1b_h);
}

__global__ void ln2_kernel(const float* __restrict__ g, const float* __restrict__ b,
                           float* __restrict__ out)
{
    add_ln_body(g_x1, g_y, g, b, out, nullptr);
}

// ---------------- MoE gate (top-1 argmax) ----------------
__global__ void zero_cnt()
{
    if (threadIdx.x < kE) g_cnt[threadIdx.x] = 0;
}

__global__ void gate_kernel(const float* __restrict__ Wg, const float* __restrict__ bg)
{
    int t = blockIdx.x, tid = threadIdx.x;
    float a0 = 0.f, a1 = 0.f, a2 = 0.f, a3 = 0.f;
    const float* xr = g_x1 + (size_t)t * kD;
    for (int d = tid; d < kD; d += 128) {
        float xv = xr[d];
        float4 w = ((const float4*)Wg)[d];
        a0 = fmaf(xv, w.x, a0);
        a1 = fmaf(xv, w.y, a1);
        a2 = fmaf(xv, w.z, a2);
        a3 = fmaf(xv, w.w, a3);
    }
    __shared__ float rsm[4][128];
    rsm[0][tid] = a0; rsm[1][tid] = a1; rsm[2][tid] = a2; rsm[3][tid] = a3;
    __syncthreads();
    for (int s = 64; s > 0; s >>= 1) {
        if (tid < s) {
            #pragma unroll
            for (int e = 0; e < 4; e++) rsm[e][tid] += rsm[e][tid + s];
        }
        __syncthreads();
    }
    if (tid == 0) {
        float sc[4];
        #pragma unroll
        for (int e = 0; e < 4; e++) sc[e] = rsm[e][0] + bg[e];
        int best = 0; float bvv = sc[0];
        #pragma unroll
        for (int e = 1; e < 4; e++) {
            if (sc[e] > bvv) { bvv = sc[e]; best = e; }
        }
        int pos = atomicAdd(&g_cnt[best], 1);
        g_list[best * kNT + pos] = t;
    }
}

// ---------------- launch ----------------
extern "C" void kernel_launch(void* const* d_in, const int* in_sizes, int n_in,
                              void* d_out, int out_size)
{
    const float* x    = (const float*)d_in[0];
    const float* Wq   = (const float*)d_in[2];
    const float* bq   = (const float*)d_in[3];
    const float* Wk   = (const float*)d_in[4];
    const float* bk   = (const float*)d_in[5];
    const float* Wv   = (const float*)d_in[6];
    const float* bv   = (const float*)d_in[7];
    const float* Wo   = (const float*)d_in[8];
    const float* bo   = (const float*)d_in[9];
    const float* ln1g = (const float*)d_in[10];
    const float* ln1b = (const float*)d_in[11];
    const float* Wg   = (const float*)d_in[12];
    const float* bg   = (const float*)d_in[13];
    const float* W1e  = (const float*)d_in[14];
    const float* b1e  = (const float*)d_in[15];
    const float* W2e  = (const float*)d_in[16];
    const float* b2e  = (const float*)d_in[17];
    const float* ln2g = (const float*)d_in[18];
    const float* ln2b = (const float*)d_in[19];
    float* out = (float*)d_out;

    cudaFuncSetAttribute(attn_tc, cudaFuncAttributeMaxDynamicSharedMemorySize, ATTN_SMEM);
    cudaFuncSetAttribute(qkv_tc,  cudaFuncAttributeMaxDynamicSharedMemorySize, GEMM_SMEM);
    cudaFuncSetAttribute(proj_tc, cudaFuncAttributeMaxDynamicSharedMemorySize, GEMM_SMEM);
    cudaFuncSetAttribute(moe1_tc, cudaFuncAttributeMaxDynamicSharedMemorySize, GEMM_SMEM);
    cudaFuncSetAttribute(moe2_tc, cudaFuncAttributeMaxDynamicSharedMemorySize, GEMM_SMEM);

    // side stream for prep work that can overlap the main chain
    cudaStream_t side;
    cudaEvent_t evFork, evJoin1, evJoin2;
    cudaStreamCreateWithFlags(&side, cudaStreamNonBlocking);
    cudaEventCreateWithFlags(&evFork, cudaEventDisableTiming);
    cudaEventCreateWithFlags(&evJoin1, cudaEventDisableTiming);
    cudaEventCreateWithFlags(&evJoin2, cudaEventDisableTiming);

    cudaEventRecord(evFork, 0);
    cudaStreamWaitEvent(side, evFork, 0);
    convert_x<<<kNT * kD / 4 / 256, 256, 0, side>>>(x);
    cudaEventRecord(evJoin1, side);
    transpose_w1<<<dim3(kFF/32, kD/32, kE), dim3(32, 8), 0, side>>>(W1e);
    transpose_w2<<<dim3(kD/32, kFF/32, kE), dim3(32, 8), 0, side>>>(W2e);
    cudaEventRecord(evJoin2, side);

    // main chain: attention path
    transpose_qkvo<<<dim3(kD/32, kD/32, 4), dim3(32, 8)>>>(Wq, Wk, Wv, Wo);
    cudaStreamWaitEvent(0, evJoin1, 0);
    qkv_tc<<<dim3(kD/128, kNT/128, 3), 256, GEMM_SMEM>>>(bq, bk, bv);
    attn_tc<<<dim3(kT/256, kB*kH), 256, ATTN_SMEM>>>();
    proj_tc<<<dim3(kD/128, kNT/128), 256, GEMM_SMEM>>>(bo);
    ln1_kernel<<<kNT, 256>>>(x, ln1g, ln1b);

    // MoE path
    zero_cnt<<<1, 32>>>();
    gate_kernel<<<kNT, 128>>>(Wg, bg);
    cudaStreamWaitEvent(0, evJoin2, 0);
    moe1_tc<<<dim3(kFF/128, kNT/128, kE), 256, GEMM_SMEM>>>(b1e);
    moe2_tc<<<dim3(kD/128, kNT/128, kE), 256, GEMM_SMEM>>>(b2e);
    ln2_kernel<<<kNT, 256>>>(ln2g, ln2b, out);
}

// round 13
// speedup vs baseline: 1.2863x; 1.2863x over previous
#include <cuda_runtime.h>
#include <cuda_fp16.h>
#include <math.h>
#include <stdint.h>

// ---------------- problem constants ----------------
constexpr int kB  = 2;
constexpr int kT  = 2048;
constexpr int kD  = 1024;
constexpr int kH  = 16;
constexpr int kDH = 64;
constexpr int kFF = 4096;
constexpr int kE  = 4;
constexpr int kNT = kB * kT;           // 4096 tokens
constexpr float kEPS = 1e-5f;

// ---------------- scratch (device globals: allocation-free) ----------------
__device__ float g_proj[kNT * kD];
__device__ float g_x1[kNT * kD];
__device__ float g_y[kNT * kD];
__device__ int   g_cnt[kE];
__device__ int   g_list[kE * kNT];

// fp16 planes: A-side arrays hi only; K/V and weights hi+lo
__device__ __half g_xb_h[kNT * kD];
__device__ __half g_qb_h[kNT * kD];
__device__ __half g_kb_h[kNT * kD],  g_kb_l[kNT * kD];
__device__ __half g_vb_h[kNT * kD],  g_vb_l[kNT * kD];
__device__ __half g_ab_h[kNT * kD];
__device__ __half g_x1b_h[kNT * kD];
__device__ __half g_hb_h[(size_t)kNT * kFF];

__device__ __half g_w4t_h[4 * kD * kD], g_w4t_l[4 * kD * kD];   // Wq,Wk,Wv,Wo [N][K]
__device__ __half g_w1t_h[(size_t)kE * kFF * kD];               // hi only (MoE)
__device__ __half g_w2t_h[(size_t)kE * kFF * kD];               // hi only (MoE)

// ==================== PTX helpers (base sm_103 features only) ====================
__device__ __forceinline__ uint32_t smem_u32(const void* p) {
    uint32_t a;
    asm("{ .reg .u64 t; cvta.to.shared.u64 t, %1; cvt.u32.u64 %0, t; }" : "=r"(a) : "l"(p));
    return a;
}

__device__ __forceinline__ void cp_async16(uint32_t s, const void* g, int sz) {
    asm volatile("cp.async.cg.shared.global [%0], [%1], 16, %2;"
                 :: "r"(s), "l"(g), "r"(sz) : "memory");
}
#define CP_COMMIT()  asm volatile("cp.async.commit_group;" ::: "memory")
#define CP_WAIT(n)   asm volatile("cp.async.wait_group %0;" :: "n"(n) : "memory")

__device__ __forceinline__ void ldsm_x4(uint32_t& r0, uint32_t& r1, uint32_t& r2,
                                        uint32_t& r3, uint32_t addr) {
    asm volatile("ldmatrix.sync.aligned.m8n8.x4.shared.b16 {%0,%1,%2,%3}, [%4];"
                 : "=r"(r0), "=r"(r1), "=r"(r2), "=r"(r3) : "r"(addr));
}
__device__ __forceinline__ void ldsm_x4_t(uint32_t& r0, uint32_t& r1, uint32_t& r2,
                                          uint32_t& r3, uint32_t addr) {
    asm volatile("ldmatrix.sync.aligned.m8n8.x4.trans.shared.b16 {%0,%1,%2,%3}, [%4];"
                 : "=r"(r0), "=r"(r1), "=r"(r2), "=r"(r3) : "r"(addr));
}

__device__ __forceinline__ void mma16816(float* d, const uint32_t* a,
                                         uint32_t b0, uint32_t b1) {
    asm volatile("mma.sync.aligned.m16n8k16.row.col.f32.f16.f16.f32 "
                 "{%0,%1,%2,%3}, {%4,%5,%6,%7}, {%8,%9}, {%0,%1,%2,%3};"
                 : "+f"(d[0]), "+f"(d[1]), "+f"(d[2]), "+f"(d[3])
                 : "r"(a[0]), "r"(a[1]), "r"(a[2]), "r"(a[3]), "r"(b0), "r"(b1));
}

__device__ __forceinline__ uint32_t pack2h(float f0, float f1) {
    __half2 hv = __floats2half2_rn(f0, f1);
    return *reinterpret_cast<uint32_t*>(&hv);
}
__device__ __forceinline__ void split2h(float f0, float f1, uint32_t& h, uint32_t& l) {
    __half2 hv = __floats2half2_rn(f0, f1);
    float r0 = f0 - __half2float(__low2half(hv));
    float r1 = f1 - __half2float(__high2half(hv));
    __half2 lv = __floats2half2_rn(r0, r1);
    h = *reinterpret_cast<uint32_t*>(&hv);
    l = *reinterpret_cast<uint32_t*>(&lv);
}

// ==================== mma.sync fp16 GEMM (R10 layout) ====================
// Block 128x128, 256 threads (8 warps, 4Mx2N), warp tile 32x64, K-chunk 32.
// BLo=true: B = Bh + Bl (2-pass). BLo=false: hi-only (1-pass).
// Planes per stage: Ah, Bh, (Bl). XOR-swizzled 64B rows, 3-stage cp.async.
constexpr int kPlaneB = 128 * 64;              // 8192 B per plane
constexpr int kStageB = 3 * kPlaneB;           // 24576 (Bl plane unused when !BLo)
constexpr int GEMM_SMEM = 3 * kStageB;         // 73728

__device__ __forceinline__ uint32_t swz(int row, int cb) {
    return (uint32_t)(row * 64 + ((((cb >> 4) ^ ((row >> 1) & 3))) << 4));
}

struct GemmPtrs {
    const __half *aH0, *aH1;
    const __half *bH0, *bL0, *bH1, *bL1;
    int v0, v1, c8;
};

template <bool BLo>
__device__ __forceinline__ void fill_stage(uint32_t sb, int k0, const GemmPtrs& P)
{
    int row = threadIdx.x >> 2;                 // 0..63
    int cb  = (threadIdx.x & 3) * 16;
    uint32_t o0 = swz(row, cb);
    uint32_t o1 = o0 + 64 * 64;
    int g = k0 + P.c8;
    cp_async16(sb + o0,             P.aH0 + g, P.v0 ? 16 : 0);
    cp_async16(sb + o1,             P.aH1 + g, P.v1 ? 16 : 0);
    cp_async16(sb + kPlaneB + o0,   P.bH0 + g, 16);
    cp_async16(sb + kPlaneB + o1,   P.bH1 + g, 16);
    if (BLo) {
        cp_async16(sb + 2*kPlaneB + o0, P.bL0 + g, 16);
        cp_async16(sb + 2*kPlaneB + o1, P.bL1 + g, 16);
    }
}

// mode 0: C = acc + bias (fp32)
// mode 1: relu(acc+bias) -> Chi (fp16 hi only)
// mode 2: (acc+bias)*scale -> Chi (+Clo if non-null)
template <bool BLo>
__device__ __forceinline__ void gemm_tc(
    const __half* __restrict__ Ah,
    const __half* __restrict__ Bh, const __half* __restrict__ Bl,
    const float* __restrict__ bias, int K, int count, const int* __restrict__ list,
    int mode, float* __restrict__ C,
    __half* __restrict__ Chi, __half* __restrict__ Clo, int ldc,
    float scale)
{
    extern __shared__ char sm[];
    const int tid  = threadIdx.x;
    const int wid  = tid >> 5, lane = tid & 31;
    const int rowBase = blockIdx.y * 128;
    const int colBase = blockIdx.x * 128;
    if (rowBase >= count) return;

    GemmPtrs P;
    {
        int r0 = tid >> 2;
        int gr0 = rowBase + r0, gr1 = rowBase + r0 + 64;
        P.v0 = gr0 < count;
        P.v1 = gr1 < count;
        int rr0 = P.v0 ? (list ? list[gr0] : gr0) : 0;
        int rr1 = P.v1 ? (list ? list[gr1] : gr1) : 0;
        P.aH0 = Ah + (size_t)rr0 * K;
        P.aH1 = Ah + (size_t)rr1 * K;
        P.bH0 = Bh + (size_t)(colBase + r0) * K;
        P.bH1 = Bh + (size_t)(colBase + r0 + 64) * K;
        P.bL0 = BLo ? (Bl + (size_t)(colBase + r0) * K) : nullptr;
        P.bL1 = BLo ? (Bl + (size_t)(colBase + r0 + 64) * K) : nullptr;
        P.c8  = (tid & 3) * 8;
    }
    const uint32_t smb = smem_u32(sm);

    // 4M x 2N warp grid: warp tile 32x64 (R10 proven layout)
    const int wM = (wid & 3) * 32;
    const int wN = (wid >> 2) * 64;

    float acc[2][8][4];
    #pragma unroll
    for (int i = 0; i < 2; i++)
        #pragma unroll
        for (int j = 0; j < 8; j++)
            #pragma unroll
            for (int d = 0; d < 4; d++) acc[i][j][d] = 0.f;

    const int aCol = (lane >> 4) * 16;
    const int bRow = (lane & 7) + ((lane >> 4) & 1) * 8;
    const int bCol = ((lane >> 3) & 1) * 16;
    uint32_t offA[2][2], offB[4][2];
    #pragma unroll
    for (int mi = 0; mi < 2; mi++)
        #pragma unroll
        for (int s = 0; s < 2; s++)
            offA[mi][s] = swz(wM + mi * 16 + (lane & 15), s * 32 + aCol);
    #pragma unroll
    for (int nj = 0; nj < 4; nj++)
        #pragma unroll
        for (int s = 0; s < 2; s++)
            offB[nj][s] = kPlaneB + swz(wN + nj * 16 + bRow, s * 32 + bCol);

    const int nc = K / 32;
    fill_stage<BLo>(smb, 0, P);
    CP_COMMIT();
    fill_stage<BLo>(smb + kStageB, 32, P);
    CP_COMMIT();

    int buf = 0;
    for (int c = 0; c < nc; c++) {
        if (c + 1 < nc) { CP_WAIT(1); } else { CP_WAIT(0); }
        __syncthreads();
        if (c + 2 < nc) {
            int nb = buf + 2; if (nb >= 3) nb -= 3;
            fill_stage<BLo>(smb + nb * kStageB, (c + 2) * 32, P);
            CP_COMMIT();
        }

        uint32_t st = smb + buf * kStageB;
        #pragma unroll
        for (int s = 0; s < 2; s++) {
            uint32_t ah[2][4];
            #pragma unroll
            for (int mi = 0; mi < 2; mi++)
                ldsm_x4(ah[mi][0], ah[mi][1], ah[mi][2], ah[mi][3], st + offA[mi][s]);
            #pragma unroll
            for (int njp = 0; njp < 4; njp++) {
                uint32_t rb = st + offB[njp][s];
                uint32_t bh[4];
                ldsm_x4(bh[0], bh[1], bh[2], bh[3], rb);
                if (BLo) {
                    uint32_t bl[4];
                    ldsm_x4(bl[0], bl[1], bl[2], bl[3], rb + kPlaneB);
                    #pragma unroll
                    for (int mi = 0; mi < 2; mi++) {
                        #pragma unroll
                        for (int half = 0; half < 2; half++) {
                            float* d = acc[mi][njp * 2 + half];
                            mma16816(d, ah[mi], bh[half * 2], bh[half * 2 + 1]);
                            mma16816(d, ah[mi], bl[half * 2], bl[half * 2 + 1]);
                        }
                    }
                } else {
                    #pragma unroll
                    for (int mi = 0; mi < 2; mi++) {
                        #pragma unroll
                        for (int half = 0; half < 2; half++) {
                            float* d = acc[mi][njp * 2 + half];
                            mma16816(d, ah[mi], bh[half * 2], bh[half * 2 + 1]);
                        }
                    }
                }
            }
        }
        buf = (buf < 2) ? buf + 1 : 0;
    }

    #pragma unroll
    for (int mi = 0; mi < 2; mi++) {
        #pragma unroll
        for (int dd = 0; dd < 2; dd++) {
            int lrow = rowBase + wM + mi * 16 + (lane >> 2) + dd * 8;
            if (lrow >= count) continue;
            int orow = list ? list[lrow] : lrow;
            #pragma unroll
            for (int nj = 0; nj < 8; nj++) {
                int n = colBase + wN + nj * 8 + (lane & 3) * 2;
                float v0 = acc[mi][nj][dd * 2 + 0] + bias[n];
                float v1 = acc[mi][nj][dd * 2 + 1] + bias[n + 1];
                if (mode == 0) {
                    *reinterpret_cast<float2*>(C + (size_t)orow * ldc + n)
                        = make_float2(v0, v1);
                } else {
                    if (mode == 1) { v0 = fmaxf(v0, 0.f); v1 = fmaxf(v1, 0.f); }
                    else           { v0 *= scale; v1 *= scale; }
                    size_t o = (size_t)orow * ldc + n;
                    if (Clo) {
                        uint32_t hh, ll;
                        split2h(v0, v1, hh, ll);
                        *reinterpret_cast<uint32_t*>(Chi + o) = hh;
                        *reinterpret_cast<uint32_t*>(Clo + o) = ll;
                    } else {
                        *reinterpret_cast<uint32_t*>(Chi + o) = pack2h(v0, v1);
                    }
                }
            }
        }
    }
}

// ---------------- GEMM wrappers ----------------
__global__ void __launch_bounds__(256, 2) qkv_tc(const float* bq, const float* bk, const float* bv)
{
    int z = blockIdx.z;
    const __half* bh = g_w4t_h + (size_t)z * kD * kD;
    const __half* bl = g_w4t_l + (size_t)z * kD * kD;
    __half* ch = (z == 0) ? g_qb_h : (z == 1) ? g_kb_h : g_vb_h;
    __half* cl = (z == 0) ? nullptr : (z == 1) ? g_kb_l : g_vb_l;
    const float* bias = (z == 0) ? bq : (z == 1) ? bk : bv;
    float scale = (z == 0) ? 0.125f : 1.0f;
    gemm_tc<true>(g_xb_h, bh, bl, bias, kD, kNT, nullptr, 2, nullptr, ch, cl, kD, scale);
}

__global__ void __launch_bounds__(256, 2) proj_tc(const float* bo)
{
    gemm_tc<true>(g_ab_h, g_w4t_h + (size_t)3 * kD * kD, g_w4t_l + (size_t)3 * kD * kD,
                  bo, kD, kNT, nullptr, 0, g_proj, nullptr, nullptr, kD, 1.f);
}

__global__ void __launch_bounds__(256, 2) moe1_tc(const float* b1e)
{
    int e = blockIdx.z;
    int cnt = g_cnt[e];
    gemm_tc<false>(g_x1b_h,
                   g_w1t_h + (size_t)e * kFF * kD, nullptr,
                   b1e + (size_t)e * kFF, kD, cnt, g_list + e * kNT,
                   1, nullptr, g_hb_h, nullptr, kFF, 1.f);
}

__global__ void __launch_bounds__(256, 2) moe2_tc(const float* b2e)
{
    int e = blockIdx.z;
    int cnt = g_cnt[e];
    gemm_tc<false>(g_hb_h,
                   g_w2t_h + (size_t)e * kFF * kD, nullptr,
                   b2e + (size_t)e * kD, kFF, cnt, g_list + e * kNT,
                   0, g_y, nullptr, nullptr, kD, 1.f);
}

// ==================== HMMA flash attention (causal, 2-pass fp16, R10 form) ====================
// Q pre-scaled by 0.125. q-tile 128 (8 warps x 16 rows), kv-tile 64.
constexpr int kARS    = 144;                   // padded row bytes
constexpr int kAPlane = 64 * kARS;             // 9216
constexpr int kAStage = 4 * kAPlane;           // Kh Kl Vh Vl = 36864
constexpr int ATTN_SMEM = 2 * kAStage;         // 73728

__device__ __forceinline__ void fill_kv(uint32_t dst, int b, int h, int kbase)
{
    const __half* srcs[4] = {g_kb_h, g_kb_l, g_vb_h, g_vb_l};
    #pragma unroll
    for (int i = 0; i < 8; i++) {
        int lin = threadIdx.x + 256 * i;
        int ch = lin & 7, row = (lin >> 3) & 63, pl = lin >> 9;
        const __half* src = srcs[pl]
            + ((size_t)(b * kT + kbase + row) * kD + h * 64 + ch * 8);
        cp_async16(dst + pl * kAPlane + row * kARS + ch * 16, src, 16);
    }
}

__global__ void __launch_bounds__(256) attn_tc()
{
    extern __shared__ char sa[];
    const uint32_t smb = smem_u32(sa);
    const int tid = threadIdx.x, wid = tid >> 5, lane = tid & 31;
    const int qt = gridDim.x - 1 - blockIdx.x;   // longest-first
    const int bh = blockIdx.y;
    const int b = bh >> 4, h = bh & 15;
    const int qb = qt * 128;
    const int wr0 = qb + wid * 16;

    // ---- load Q tile (128 x 64, hi only) into stage1 region ----
    #pragma unroll
    for (int i = 0; i < 4; i++) {
        int lin = tid + 256 * i;
        int ch = lin & 7, row = lin >> 3;
        const __half* src = g_qb_h
            + ((size_t)(b * kT + qb + row) * kD + h * 64 + ch * 8);
        cp_async16(smb + kAStage + row * kARS + ch * 16, src, 16);
    }
    CP_COMMIT();
    fill_kv(smb, b, h, 0);
    CP_COMMIT();
    CP_WAIT(0);
    __syncthreads();

    // ---- Q fragments to registers ----
    uint32_t qh[4][4];
    #pragma unroll
    for (int ks = 0; ks < 4; ks++) {
        uint32_t addr = smb + kAStage + (wid * 16 + (lane & 15)) * kARS
                      + ks * 32 + (lane >> 4) * 16;
        ldsm_x4(qh[ks][0], qh[ks][1], qh[ks][2], qh[ks][3], addr);
    }

    float m0 = -1e30f, m1 = -1e30f, l0 = 0.f, l1 = 0.f;
    float o[8][4];
    #pragma unroll
    for (int g = 0; g < 8; g++)
        #pragma unroll
        for (int d = 0; d < 4; d++) o[g][d] = 0.f;

    const int ktmax = 2 * qt + 2;
    for (int kt = 0; kt < ktmax; kt++) {
        CP_WAIT(0);
        __syncthreads();
        if (kt + 1 < ktmax) {
            fill_kv(smb + ((kt + 1) & 1) * kAStage, b, h, (kt + 1) * 64);
            CP_COMMIT();
        }

        const int kbase = kt * 64;
        if (kbase <= wr0 + 15) {
            const uint32_t st = smb + (kt & 1) * kAStage;

            // ---- S = Q K^T (2-pass) ----
            float s[8][4];
            #pragma unroll
            for (int j = 0; j < 8; j++)
                #pragma unroll
                for (int d = 0; d < 4; d++) s[j][d] = 0.f;

            #pragma unroll
            for (int ks = 0; ks < 4; ks++) {
                #pragma unroll
                for (int ng = 0; ng < 4; ng++) {
                    uint32_t a = st + (ng * 16 + (lane & 7) + (lane >> 4) * 8) * kARS
                               + ks * 32 + ((lane >> 3) & 1) * 16;
                    uint32_t k0, k1, k2, k3, e0, e1, e2, e3;
                    ldsm_x4(k0, k1, k2, k3, a);
                    ldsm_x4(e0, e1, e2, e3, a + kAPlane);
                    mma16816(s[2*ng],   qh[ks], k0, k1);
                    mma16816(s[2*ng],   qh[ks], e0, e1);
                    mma16816(s[2*ng+1], qh[ks], k2, k3);
                    mma16816(s[2*ng+1], qh[ks], e2, e3);
                }
            }

            // ---- mask (straddling tiles only) ----
            const int r0 = wr0 + (lane >> 2), r1 = r0 + 8;
            if (kbase + 63 > wr0) {
                #pragma unroll
                for (int j = 0; j < 8; j++) {
                    int c = kbase + j * 8 + (lane & 3) * 2;
                    if (c > r0)     s[j][0] = -1e30f;
                    if (c + 1 > r0) s[j][1] = -1e30f;
                    if (c > r1)     s[j][2] = -1e30f;
                    if (c + 1 > r1) s[j][3] = -1e30f;
                }
            }

            // ---- online softmax ----
            float rm0 = -1e30f, rm1 = -1e30f;
            #pragma unroll
            for (int j = 0; j < 8; j++) {
                rm0 = fmaxf(rm0, fmaxf(s[j][0], s[j][1]));
                rm1 = fmaxf(rm1, fmaxf(s[j][2], s[j][3]));
            }
            rm0 = fmaxf(rm0, __shfl_xor_sync(0xffffffffu, rm0, 1));
            rm0 = fmaxf(rm0, __shfl_xor_sync(0xffffffffu, rm0, 2));
            rm1 = fmaxf(rm1, __shfl_xor_sync(0xffffffffu, rm1, 1));
            rm1 = fmaxf(rm1, __shfl_xor_sync(0xffffffffu, rm1, 2));
            float mn0 = fmaxf(m0, rm0), mn1 = fmaxf(m1, rm1);
            float cr0 = __expf(m0 - mn0), cr1 = __expf(m1 - mn1);
            m0 = mn0; m1 = mn1;
            float ps0 = 0.f, ps1 = 0.f;
            #pragma unroll
            for (int j = 0; j < 8; j++) {
                s[j][0] = __expf(s[j][0] - m0);
                s[j][1] = __expf(s[j][1] - m0);
                s[j][2] = __expf(s[j][2] - m1);
                s[j][3] = __expf(s[j][3] - m1);
                ps0 += s[j][0] + s[j][1];
                ps1 += s[j][2] + s[j][3];
            }
            ps0 += __shfl_xor_sync(0xffffffffu, ps0, 1);
            ps0 += __shfl_xor_sync(0xffffffffu, ps0, 2);
            ps1 += __shfl_xor_sync(0xffffffffu, ps1, 1);
            ps1 += __shfl_xor_sync(0xffffffffu, ps1, 2);
            l0 = l0 * cr0 + ps0;
            l1 = l1 * cr1 + ps1;
            #pragma unroll
            for (int g = 0; g < 8; g++) {
                o[g][0] *= cr0; o[g][1] *= cr0;
                o[g][2] *= cr1; o[g][3] *= cr1;
            }

            // ---- O += P V (2-pass, P packed in registers) ----
            #pragma unroll
            for (int t = 0; t < 4; t++) {
                uint32_t ph[4];
                ph[0] = pack2h(s[2*t][0],   s[2*t][1]);
                ph[1] = pack2h(s[2*t][2],   s[2*t][3]);
                ph[2] = pack2h(s[2*t+1][0], s[2*t+1][1]);
                ph[3] = pack2h(s[2*t+1][2], s[2*t+1][3]);
                #pragma unroll
                for (int dg = 0; dg < 4; dg++) {
                    uint32_t a = st + 2 * kAPlane
                               + (t * 16 + (lane & 7) + ((lane >> 3) & 1) * 8) * kARS
                               + dg * 32 + (lane >> 4) * 16;
                    uint32_t v0, v1, v2, v3, w0, w1, w2, w3;
                    ldsm_x4_t(v0, v1, v2, v3, a);
                    ldsm_x4_t(w0, w1, w2, w3, a + kAPlane);
                    mma16816(o[2*dg],   ph, v0, v1);
                    mma16816(o[2*dg],   ph, w0, w1);
                    mma16816(o[2*dg+1], ph, v2, v3);
                    mma16816(o[2*dg+1], ph, w2, w3);
                }
            }
        }
    }

    // ---- epilogue: O/l -> fp16 hi plane ----
    const float inv0 = 1.f / l0, inv1 = 1.f / l1;
    const size_t tok0 = (size_t)(b * kT) + wr0 + (lane >> 2);
    #pragma unroll
    for (int g = 0; g < 8; g++) {
        int col = h * 64 + g * 8 + (lane & 3) * 2;
        *reinterpret_cast<uint32_t*>(g_ab_h + tok0 * kD + col)
            = pack2h(o[g][0] * inv0, o[g][1] * inv0);
        *reinterpret_cast<uint32_t*>(g_ab_h + (tok0 + 8) * kD + col)
            = pack2h(o[g][2] * inv1, o[g][3] * inv1);
    }
}

// ---------------- conversion kernels ----------------
__global__ void convert_x(const float* __restrict__ x)
{
    int i = blockIdx.x * 256 + threadIdx.x;
    float4 v = ((const float4*)x)[i];
    size_t o = (size_t)i * 4;
    *reinterpret_cast<uint32_t*>(g_xb_h + o)     = pack2h(v.x, v.y);
    *reinterpret_cast<uint32_t*>(g_xb_h + o + 2) = pack2h(v.z, v.w);
}

// hi+lo transpose (attention-path weights)
__device__ __forceinline__ void transpose_body(
    const float* __restrict__ src, __half* __restrict__ hi,
    __half* __restrict__ lo, int K, int N)
{
    __shared__ float tile[32][33];
    int bn = blockIdx.x * 32, bk = blockIdx.y * 32;
    int tx = threadIdx.x, ty = threadIdx.y;
    #pragma unroll
    for (int i = 0; i < 32; i += 8)
        tile[ty + i][tx] = src[(size_t)(bk + ty + i) * N + bn + tx];
    __syncthreads();
    #pragma unroll
    for (int i = 0; i < 32; i += 8) {
        float v = tile[tx][ty + i];
        __half hh = __float2half_rn(v);
        size_t o = (size_t)(bn + ty + i) * K + bk + tx;
        hi[o] = hh;
        if (lo) lo[o] = __float2half_rn(v - __half2float(hh));
    }
}

__global__ void transpose_qkvo(const float* Wq, const float* Wk, const float* Wv, const float* Wo)
{
    int z = blockIdx.z;
    const float* src = (z == 0) ? Wq : (z == 1) ? Wk : (z == 2) ? Wv : Wo;
    transpose_body(src, g_w4t_h + (size_t)z * kD * kD, g_w4t_l + (size_t)z * kD * kD, kD, kD);
}

__global__ void transpose_w1(const float* W1e)
{
    int e = blockIdx.z;
    size_t off = (size_t)e * kD * kFF;
    transpose_body(W1e + off, g_w1t_h + off, nullptr, kD, kFF);
}

__global__ void transpose_w2(const float* W2e)
{
    int e = blockIdx.z;
    size_t off = (size_t)e * kFF * kD;
    transpose_body(W2e + off, g_w2t_h + off, nullptr, kFF, kD);
}

// ---------------- add + layernorm ----------------
__device__ __forceinline__ float block_sum_256(float v, float* red)
{
    int tid = threadIdx.x;
    #pragma unroll
    for (int o = 16; o; o >>= 1) v += __shfl_xor_sync(0xffffffffu, v, o);
    if ((tid & 31) == 0) red[tid >> 5] = v;
    __syncthreads();
    if (tid < 8) {
        float x = red[tid];
        #pragma unroll
        for (int o = 4; o; o >>= 1) x += __shfl_xor_sync(0xffu, x, o);
        if (tid == 0) red[0] = x;
    }
    __syncthreads();
    float r = red[0];
    __syncthreads();
    return r;
}

__device__ __forceinline__ void add_ln_body(
    const float* __restrict__ A, const float* __restrict__ Bb,
    const float* __restrict__ gw, const float* __restrict__ bw,
    float* __restrict__ out, __half* __restrict__ oh)
{
    __shared__ float red[8];
    int t = blockIdx.x, tid = threadIdx.x;
    float4 av = ((const float4*)(A  + (size_t)t * kD))[tid];
    float4 bv = ((const float4*)(Bb + (size_t)t * kD))[tid];
    float vx = av.x + bv.x, vy = av.y + bv.y, vz = av.z + bv.z, vw = av.w + bv.w;
    float ssum = block_sum_256(vx + vy + vz + vw, red);
    float mu = ssum * (1.0f / kD);
    float dx = vx - mu, dy = vy - mu, dz = vz - mu, dw = vw - mu;
    float sq = block_sum_256(dx*dx + dy*dy + dz*dz + dw*dw, red);
    float rstd = rsqrtf(sq * (1.0f / kD) + kEPS);
    float4 gv = ((const float4*)gw)[tid];
    float4 be = ((const float4*)bw)[tid];
    float ovv[4] = {dx*rstd*gv.x + be.x, dy*rstd*gv.y + be.y,
                    dz*rstd*gv.z + be.z, dw*rstd*gv.w + be.w};
    ((float4*)(out + (size_t)t * kD))[tid] = make_float4(ovv[0], ovv[1], ovv[2], ovv[3]);
    if (oh) {
        size_t o = (size_t)t * kD + tid * 4;
        *reinterpret_cast<uint32_t*>(oh + o)     = pack2h(ovv[0], ovv[1]);
        *reinterpret_cast<uint32_t*>(oh + o + 2) = pack2h(ovv[2], ovv[3]);
    }
}

__global__ void ln1_kernel(const float* __restrict__ x,
                           const float* __restrict__ g, const float* __restrict__ b)
{
    add_ln_body(x, g_proj, g, b, g_x1, g_x1b_h);
}

__global__ void ln2_kernel(const float* __restrict__ g, const float* __restrict__ b,
                           float* __restrict__ out)
{
    add_ln_body(g_x1, g_y, g, b, out, nullptr);
}

// ---------------- MoE gate (top-1 argmax) ----------------
__global__ void zero_cnt()
{
    if (threadIdx.x < kE) g_cnt[threadIdx.x] = 0;
}

__global__ void gate_kernel(const float* __restrict__ Wg, const float* __restrict__ bg)
{
    int t = blockIdx.x, tid = threadIdx.x;
    float a0 = 0.f, a1 = 0.f, a2 = 0.f, a3 = 0.f;
    const float* xr = g_x1 + (size_t)t * kD;
    for (int d = tid; d < kD; d += 128) {
        float xv = xr[d];
        float4 w = ((const float4*)Wg)[d];
        a0 = fmaf(xv, w.x, a0);
        a1 = fmaf(xv, w.y, a1);
        a2 = fmaf(xv, w.z, a2);
        a3 = fmaf(xv, w.w, a3);
    }
    __shared__ float rsm[4][128];
    rsm[0][tid] = a0; rsm[1][tid] = a1; rsm[2][tid] = a2; rsm[3][tid] = a3;
    __syncthreads();
    for (int s = 64; s > 0; s >>= 1) {
        if (tid < s) {
            #pragma unroll
            for (int e = 0; e < 4; e++) rsm[e][tid] += rsm[e][tid + s];
        }
        __syncthreads();
    }
    if (tid == 0) {
        float sc[4];
        #pragma unroll
        for (int e = 0; e < 4; e++) sc[e] = rsm[e][0] + bg[e];
        int best = 0; float bvv = sc[0];
        #pragma unroll
        for (int e = 1; e < 4; e++) {
            if (sc[e] > bvv) { bvv = sc[e]; best = e; }
        }
        int pos = atomicAdd(&g_cnt[best], 1);
        g_list[best * kNT + pos] = t;
    }
}

// ---------------- launch ----------------
extern "C" void kernel_launch(void* const* d_in, const int* in_sizes, int n_in,
                              void* d_out, int out_size)
{
    const float* x    = (const float*)d_in[0];
    const float* Wq   = (const float*)d_in[2];
    const float* bq   = (const float*)d_in[3];
    const float* Wk   = (const float*)d_in[4];
    const float* bk   = (const float*)d_in[5];
    const float* Wv   = (const float*)d_in[6];
    const float* bv   = (const float*)d_in[7];
    const float* Wo   = (const float*)d_in[8];
    const float* bo   = (const float*)d_in[9];
    const float* ln1g = (const float*)d_in[10];
    const float* ln1b = (const float*)d_in[11];
    const float* Wg   = (const float*)d_in[12];
    const float* bg   = (const float*)d_in[13];
    const float* W1e  = (const float*)d_in[14];
    const float* b1e  = (const float*)d_in[15];
    const float* W2e  = (const float*)d_in[16];
    const float* b2e  = (const float*)d_in[17];
    const float* ln2g = (const float*)d_in[18];
    const float* ln2b = (const float*)d_in[19];
    float* out = (float*)d_out;

    cudaFuncSetAttribute(attn_tc, cudaFuncAttributeMaxDynamicSharedMemorySize, ATTN_SMEM);
    cudaFuncSetAttribute(qkv_tc,  cudaFuncAttributeMaxDynamicSharedMemorySize, GEMM_SMEM);
    cudaFuncSetAttribute(proj_tc, cudaFuncAttributeMaxDynamicSharedMemorySize, GEMM_SMEM);
    cudaFuncSetAttribute(moe1_tc, cudaFuncAttributeMaxDynamicSharedMemorySize, GEMM_SMEM);
    cudaFuncSetAttribute(moe2_tc, cudaFuncAttributeMaxDynamicSharedMemorySize, GEMM_SMEM);

    // side stream for prep work that can overlap the main chain
    cudaStream_t side;
    cudaEvent_t evFork, evJoin1, evJoin2;
    cudaStreamCreateWithFlags(&side, cudaStreamNonBlocking);
    cudaEventCreateWithFlags(&evFork, cudaEventDisableTiming);
    cudaEventCreateWithFlags(&evJoin1, cudaEventDisableTiming);
    cudaEventCreateWithFlags(&evJoin2, cudaEventDisableTiming);

    cudaEventRecord(evFork, 0);
    cudaStreamWaitEvent(side, evFork, 0);
    convert_x<<<kNT * kD / 4 / 256, 256, 0, side>>>(x);
    cudaEventRecord(evJoin1, side);
    transpose_w1<<<dim3(kFF/32, kD/32, kE), dim3(32, 8), 0, side>>>(W1e);
    transpose_w2<<<dim3(kD/32, kFF/32, kE), dim3(32, 8), 0, side>>>(W2e);
    cudaEventRecord(evJoin2, side);

    // main chain: attention path
    transpose_qkvo<<<dim3(kD/32, kD/32, 4), dim3(32, 8)>>>(Wq, Wk, Wv, Wo);
    cudaStreamWaitEvent(0, evJoin1, 0);
    qkv_tc<<<dim3(kD/128, kNT/128, 3), 256, GEMM_SMEM>>>(bq, bk, bv);
    attn_tc<<<dim3(kT/128, kB*kH), 256, ATTN_SMEM>>>();
    proj_tc<<<dim3(kD/128, kNT/128), 256, GEMM_SMEM>>>(bo);
    ln1_kernel<<<kNT, 256>>>(x, ln1g, ln1b);

    // MoE path
    zero_cnt<<<1, 32>>>();
    gate_kernel<<<kNT, 128>>>(Wg, bg);
    cudaStreamWaitEvent(0, evJoin2, 0);
    moe1_tc<<<dim3(kFF/128, kNT/128, kE), 256, GEMM_SMEM>>>(b1e);
    moe2_tc<<<dim3(kD/128, kNT/128, kE), 256, GEMM_SMEM>>>(b2e);
    ln2_kernel<<<kNT, 256>>>(ln2g, ln2b, out);
}

// round 14
// speedup vs baseline: 1.5904x; 1.2364x over previous
#include <cuda_runtime.h>
#include <cuda_fp16.h>
#include <math.h>
#include <stdint.h>

// ---------------- problem constants ----------------
constexpr int kB  = 2;
constexpr int kT  = 2048;
constexpr int kD  = 1024;
constexpr int kH  = 16;
constexpr int kDH = 64;
constexpr int kFF = 4096;
constexpr int kE  = 4;
constexpr int kNT = kB * kT;           // 4096 tokens
constexpr float kEPS = 1e-5f;

// ---------------- scratch (device globals: allocation-free) ----------------
__device__ float g_proj[kNT * kD];
__device__ float g_x1[kNT * kD];
__device__ float g_y[kNT * kD];
__device__ int   g_cnt[kE];
__device__ int   g_list[kE * kNT];

// fp16 planes (hi-only activations; K/V hi-only now)
__device__ __half g_xb_h[kNT * kD];
__device__ __half g_qb_h[kNT * kD];
__device__ __half g_kb_h[kNT * kD];
__device__ __half g_vb_h[kNT * kD];
__device__ __half g_ab_h[kNT * kD];
__device__ __half g_x1b_h[kNT * kD];
__device__ __half g_hb_h[(size_t)kNT * kFF];

__device__ __half g_w4t_h[4 * kD * kD], g_w4t_l[4 * kD * kD];   // Wq,Wk,Wv,Wo [N][K]
__device__ __half g_w1t_h[(size_t)kE * kFF * kD];               // hi only (MoE)
__device__ __half g_w2t_h[(size_t)kE * kFF * kD];               // hi only (MoE)

// ==================== PTX helpers (base sm_103 features only) ====================
__device__ __forceinline__ uint32_t smem_u32(const void* p) {
    uint32_t a;
    asm("{ .reg .u64 t; cvta.to.shared.u64 t, %1; cvt.u32.u64 %0, t; }" : "=r"(a) : "l"(p));
    return a;
}

__device__ __forceinline__ void cp_async16(uint32_t s, const void* g, int sz) {
    asm volatile("cp.async.cg.shared.global [%0], [%1], 16, %2;"
                 :: "r"(s), "l"(g), "r"(sz) : "memory");
}
#define CP_COMMIT()  asm volatile("cp.async.commit_group;" ::: "memory")
#define CP_WAIT(n)   asm volatile("cp.async.wait_group %0;" :: "n"(n) : "memory")

__device__ __forceinline__ void ldsm_x4(uint32_t& r0, uint32_t& r1, uint32_t& r2,
                                        uint32_t& r3, uint32_t addr) {
    asm volatile("ldmatrix.sync.aligned.m8n8.x4.shared.b16 {%0,%1,%2,%3}, [%4];"
                 : "=r"(r0), "=r"(r1), "=r"(r2), "=r"(r3) : "r"(addr));
}
__device__ __forceinline__ void ldsm_x4_t(uint32_t& r0, uint32_t& r1, uint32_t& r2,
                                          uint32_t& r3, uint32_t addr) {
    asm volatile("ldmatrix.sync.aligned.m8n8.x4.trans.shared.b16 {%0,%1,%2,%3}, [%4];"
                 : "=r"(r0), "=r"(r1), "=r"(r2), "=r"(r3) : "r"(addr));
}

__device__ __forceinline__ void mma16816(float* d, const uint32_t* a,
                                         uint32_t b0, uint32_t b1) {
    asm volatile("mma.sync.aligned.m16n8k16.row.col.f32.f16.f16.f32 "
                 "{%0,%1,%2,%3}, {%4,%5,%6,%7}, {%8,%9}, {%0,%1,%2,%3};"
                 : "+f"(d[0]), "+f"(d[1]), "+f"(d[2]), "+f"(d[3])
                 : "r"(a[0]), "r"(a[1]), "r"(a[2]), "r"(a[3]), "r"(b0), "r"(b1));
}

__device__ __forceinline__ uint32_t pack2h(float f0, float f1) {
    __half2 hv = __floats2half2_rn(f0, f1);
    return *reinterpret_cast<uint32_t*>(&hv);
}
__device__ __forceinline__ void split2h(float f0, float f1, uint32_t& h, uint32_t& l) {
    __half2 hv = __floats2half2_rn(f0, f1);
    float r0 = f0 - __half2float(__low2half(hv));
    float r1 = f1 - __half2float(__high2half(hv));
    __half2 lv = __floats2half2_rn(r0, r1);
    h = *reinterpret_cast<uint32_t*>(&hv);
    l = *reinterpret_cast<uint32_t*>(&lv);
}

// ==================== mma.sync fp16 GEMM ====================
// Block 128x128, 256 threads (8 warps, 4Mx2N), warp tile 32x64, K-chunk 32.
// BLo=true: B = Bh + Bl (2-pass). BLo=false: hi-only (1-pass).
constexpr int kPlaneB = 128 * 64;              // 8192 B per plane
constexpr int kStageB = 3 * kPlaneB;           // 24576 (Bl plane unused when !BLo)
constexpr int GEMM_SMEM = 3 * kStageB;         // 73728

__device__ __forceinline__ uint32_t swz(int row, int cb) {
    return (uint32_t)(row * 64 + ((((cb >> 4) ^ ((row >> 1) & 3))) << 4));
}

struct GemmPtrs {
    const __half *aH0, *aH1;
    const __half *bH0, *bL0, *bH1, *bL1;
    int v0, v1, c8;
};

template <bool BLo>
__device__ __forceinline__ void fill_stage(uint32_t sb, int k0, const GemmPtrs& P)
{
    int row = threadIdx.x >> 2;                 // 0..63
    int cb  = (threadIdx.x & 3) * 16;
    uint32_t o0 = swz(row, cb);
    uint32_t o1 = o0 + 64 * 64;
    int g = k0 + P.c8;
    cp_async16(sb + o0,             P.aH0 + g, P.v0 ? 16 : 0);
    cp_async16(sb + o1,             P.aH1 + g, P.v1 ? 16 : 0);
    cp_async16(sb + kPlaneB + o0,   P.bH0 + g, 16);
    cp_async16(sb + kPlaneB + o1,   P.bH1 + g, 16);
    if (BLo) {
        cp_async16(sb + 2*kPlaneB + o0, P.bL0 + g, 16);
        cp_async16(sb + 2*kPlaneB + o1, P.bL1 + g, 16);
    }
}

// mode 0: C = acc + bias (fp32)
// mode 1: relu(acc+bias) -> Chi (fp16 hi only)
// mode 2: (acc+bias)*scale -> Chi (+Clo if non-null)
template <bool BLo>
__device__ __forceinline__ void gemm_tc(
    const __half* __restrict__ Ah,
    const __half* __restrict__ Bh, const __half* __restrict__ Bl,
    const float* __restrict__ bias, int K, int count, const int* __restrict__ list,
    int mode, float* __restrict__ C,
    __half* __restrict__ Chi, __half* __restrict__ Clo, int ldc,
    float scale)
{
    extern __shared__ char sm[];
    const int tid  = threadIdx.x;
    const int wid  = tid >> 5, lane = tid & 31;
    const int rowBase = blockIdx.y * 128;
    const int colBase = blockIdx.x * 128;
    if (rowBase >= count) return;

    GemmPtrs P;
    {
        int r0 = tid >> 2;
        int gr0 = rowBase + r0, gr1 = rowBase + r0 + 64;
        P.v0 = gr0 < count;
        P.v1 = gr1 < count;
        int rr0 = P.v0 ? (list ? list[gr0] : gr0) : 0;
        int rr1 = P.v1 ? (list ? list[gr1] : gr1) : 0;
        P.aH0 = Ah + (size_t)rr0 * K;
        P.aH1 = Ah + (size_t)rr1 * K;
        P.bH0 = Bh + (size_t)(colBase + r0) * K;
        P.bH1 = Bh + (size_t)(colBase + r0 + 64) * K;
        P.bL0 = BLo ? (Bl + (size_t)(colBase + r0) * K) : nullptr;
        P.bL1 = BLo ? (Bl + (size_t)(colBase + r0 + 64) * K) : nullptr;
        P.c8  = (tid & 3) * 8;
    }
    const uint32_t smb = smem_u32(sm);

    const int wM = (wid & 3) * 32;
    const int wN = (wid >> 2) * 64;

    float acc[2][8][4];
    #pragma unroll
    for (int i = 0; i < 2; i++)
        #pragma unroll
        for (int j = 0; j < 8; j++)
            #pragma unroll
            for (int d = 0; d < 4; d++) acc[i][j][d] = 0.f;

    const int aCol = (lane >> 4) * 16;
    const int bRow = (lane & 7) + ((lane >> 4) & 1) * 8;
    const int bCol = ((lane >> 3) & 1) * 16;
    uint32_t offA[2][2], offB[4][2];
    #pragma unroll
    for (int mi = 0; mi < 2; mi++)
        #pragma unroll
        for (int s = 0; s < 2; s++)
            offA[mi][s] = swz(wM + mi * 16 + (lane & 15), s * 32 + aCol);
    #pragma unroll
    for (int nj = 0; nj < 4; nj++)
        #pragma unroll
        for (int s = 0; s < 2; s++)
            offB[nj][s] = kPlaneB + swz(wN + nj * 16 + bRow, s * 32 + bCol);

    const int nc = K / 32;
    fill_stage<BLo>(smb, 0, P);
    CP_COMMIT();
    fill_stage<BLo>(smb + kStageB, 32, P);
    CP_COMMIT();

    int buf = 0;
    for (int c = 0; c < nc; c++) {
        if (c + 1 < nc) { CP_WAIT(1); } else { CP_WAIT(0); }
        __syncthreads();
        if (c + 2 < nc) {
            int nb = buf + 2; if (nb >= 3) nb -= 3;
            fill_stage<BLo>(smb + nb * kStageB, (c + 2) * 32, P);
            CP_COMMIT();
        }

        uint32_t st = smb + buf * kStageB;
        #pragma unroll
        for (int s = 0; s < 2; s++) {
            uint32_t ah[2][4];
            #pragma unroll
            for (int mi = 0; mi < 2; mi++)
                ldsm_x4(ah[mi][0], ah[mi][1], ah[mi][2], ah[mi][3], st + offA[mi][s]);
            #pragma unroll
            for (int njp = 0; njp < 4; njp++) {
                uint32_t rb = st + offB[njp][s];
                uint32_t bh[4];
                ldsm_x4(bh[0], bh[1], bh[2], bh[3], rb);
                if (BLo) {
                    uint32_t bl[4];
                    ldsm_x4(bl[0], bl[1], bl[2], bl[3], rb + kPlaneB);
                    #pragma unroll
                    for (int mi = 0; mi < 2; mi++) {
                        #pragma unroll
                        for (int half = 0; half < 2; half++) {
                            float* d = acc[mi][njp * 2 + half];
                            mma16816(d, ah[mi], bh[half * 2], bh[half * 2 + 1]);
                            mma16816(d, ah[mi], bl[half * 2], bl[half * 2 + 1]);
                        }
                    }
                } else {
                    #pragma unroll
                    for (int mi = 0; mi < 2; mi++) {
                        #pragma unroll
                        for (int half = 0; half < 2; half++) {
                            float* d = acc[mi][njp * 2 + half];
                            mma16816(d, ah[mi], bh[half * 2], bh[half * 2 + 1]);
                        }
                    }
                }
            }
        }
        buf = (buf < 2) ? buf + 1 : 0;
    }

    #pragma unroll
    for (int mi = 0; mi < 2; mi++) {
        #pragma unroll
        for (int dd = 0; dd < 2; dd++) {
            int lrow = rowBase + wM + mi * 16 + (lane >> 2) + dd * 8;
            if (lrow >= count) continue;
            int orow = list ? list[lrow] : lrow;
            #pragma unroll
            for (int nj = 0; nj < 8; nj++) {
                int n = colBase + wN + nj * 8 + (lane & 3) * 2;
                float v0 = acc[mi][nj][dd * 2 + 0] + bias[n];
                float v1 = acc[mi][nj][dd * 2 + 1] + bias[n + 1];
                if (mode == 0) {
                    *reinterpret_cast<float2*>(C + (size_t)orow * ldc + n)
                        = make_float2(v0, v1);
                } else {
                    if (mode == 1) { v0 = fmaxf(v0, 0.f); v1 = fmaxf(v1, 0.f); }
                    else           { v0 *= scale; v1 *= scale; }
                    size_t o = (size_t)orow * ldc + n;
                    if (Clo) {
                        uint32_t hh, ll;
                        split2h(v0, v1, hh, ll);
                        *reinterpret_cast<uint32_t*>(Chi + o) = hh;
                        *reinterpret_cast<uint32_t*>(Clo + o) = ll;
                    } else {
                        *reinterpret_cast<uint32_t*>(Chi + o) = pack2h(v0, v1);
                    }
                }
            }
        }
    }
}

// ---------------- GEMM wrappers ----------------
__global__ void __launch_bounds__(256, 2) qkv_tc(const float* bq, const float* bk, const float* bv)
{
    int z = blockIdx.z;
    const __half* bh = g_w4t_h + (size_t)z * kD * kD;
    __half* ch = (z == 0) ? g_qb_h : (z == 1) ? g_kb_h : g_vb_h;
    const float* bias = (z == 0) ? bq : (z == 1) ? bk : bv;
    float scale = (z == 0) ? 0.125f : 1.0f;
    gemm_tc<false>(g_xb_h, bh, nullptr, bias, kD, kNT, nullptr, 2,
                   nullptr, ch, nullptr, kD, scale);
}

__global__ void __launch_bounds__(256, 2) proj_tc(const float* bo)
{
    gemm_tc<true>(g_ab_h, g_w4t_h + (size_t)3 * kD * kD, g_w4t_l + (size_t)3 * kD * kD,
                  bo, kD, kNT, nullptr, 0, g_proj, nullptr, nullptr, kD, 1.f);
}

__global__ void __launch_bounds__(256, 2) moe1_tc(const float* b1e)
{
    int e = blockIdx.z;
    int cnt = g_cnt[e];
    gemm_tc<false>(g_x1b_h,
                   g_w1t_h + (size_t)e * kFF * kD, nullptr,
                   b1e + (size_t)e * kFF, kD, cnt, g_list + e * kNT,
                   1, nullptr, g_hb_h, nullptr, kFF, 1.f);
}

__global__ void __launch_bounds__(256, 2) moe2_tc(const float* b2e)
{
    int e = blockIdx.z;
    int cnt = g_cnt[e];
    gemm_tc<false>(g_hb_h,
                   g_w2t_h + (size_t)e * kFF * kD, nullptr,
                   b2e + (size_t)e * kD, kFF, cnt, g_list + e * kNT,
                   0, g_y, nullptr, nullptr, kD, 1.f);
}

// ==================== HMMA flash attention (causal, 1-pass fp16) ====================
// Q pre-scaled by 0.125. q-tile 128 (8 warps x 16 rows), kv-tile 64.
// K/V hi-only: stage = Kh + Vh planes.
constexpr int kARS    = 144;                   // padded row bytes
constexpr int kAPlane = 64 * kARS;             // 9216
constexpr int kAStage = 2 * kAPlane;           // Kh Vh = 18432
constexpr int kQOff   = 2 * kAStage;           // Q region after both stages
constexpr int ATTN_SMEM = 2 * kAStage + 128 * kARS;   // 55296

__device__ __forceinline__ void fill_kv(uint32_t dst, int b, int h, int kbase)
{
    const __half* srcs[2] = {g_kb_h, g_vb_h};
    #pragma unroll
    for (int i = 0; i < 4; i++) {
        int lin = threadIdx.x + 256 * i;
        int ch = lin & 7, row = (lin >> 3) & 63, pl = lin >> 9;
        const __half* src = srcs[pl]
            + ((size_t)(b * kT + kbase + row) * kD + h * 64 + ch * 8);
        cp_async16(dst + pl * kAPlane + row * kARS + ch * 16, src, 16);
    }
}

__global__ void __launch_bounds__(256) attn_tc()
{
    extern __shared__ char sa[];
    const uint32_t smb = smem_u32(sa);
    const int tid = threadIdx.x, wid = tid >> 5, lane = tid & 31;
    const int qt = gridDim.x - 1 - blockIdx.x;   // longest-first
    const int bh = blockIdx.y;
    const int b = bh >> 4, h = bh & 15;
    const int qb = qt * 128;
    const int wr0 = qb + wid * 16;

    // ---- load Q tile (128 x 64, hi only) ----
    #pragma unroll
    for (int i = 0; i < 4; i++) {
        int lin = tid + 256 * i;
        int ch = lin & 7, row = lin >> 3;
        const __half* src = g_qb_h
            + ((size_t)(b * kT + qb + row) * kD + h * 64 + ch * 8);
        cp_async16(smb + kQOff + row * kARS + ch * 16, src, 16);
    }
    CP_COMMIT();
    fill_kv(smb, b, h, 0);
    CP_COMMIT();
    CP_WAIT(0);
    __syncthreads();

    // ---- Q fragments to registers ----
    uint32_t qh[4][4];
    #pragma unroll
    for (int ks = 0; ks < 4; ks++) {
        uint32_t addr = smb + kQOff + (wid * 16 + (lane & 15)) * kARS
                      + ks * 32 + (lane >> 4) * 16;
        ldsm_x4(qh[ks][0], qh[ks][1], qh[ks][2], qh[ks][3], addr);
    }

    float m0 = -1e30f, m1 = -1e30f, l0 = 0.f, l1 = 0.f;
    float o[8][4];
    #pragma unroll
    for (int g = 0; g < 8; g++)
        #pragma unroll
        for (int d = 0; d < 4; d++) o[g][d] = 0.f;

    const int ktmax = 2 * qt + 2;
    for (int kt = 0; kt < ktmax; kt++) {
        CP_WAIT(0);
        __syncthreads();
        if (kt + 1 < ktmax) {
            fill_kv(smb + ((kt + 1) & 1) * kAStage, b, h, (kt + 1) * 64);
            CP_COMMIT();
        }

        const int kbase = kt * 64;
        if (kbase <= wr0 + 15) {
            const uint32_t st = smb + (kt & 1) * kAStage;

            // ---- S = Q K^T (1-pass) ----
            float s[8][4];
            #pragma unroll
            for (int j = 0; j < 8; j++)
                #pragma unroll
                for (int d = 0; d < 4; d++) s[j][d] = 0.f;

            #pragma unroll
            for (int ks = 0; ks < 4; ks++) {
                #pragma unroll
                for (int ng = 0; ng < 4; ng++) {
                    uint32_t a = st + (ng * 16 + (lane & 7) + (lane >> 4) * 8) * kARS
                               + ks * 32 + ((lane >> 3) & 1) * 16;
                    uint32_t k0, k1, k2, k3;
                    ldsm_x4(k0, k1, k2, k3, a);
                    mma16816(s[2*ng],   qh[ks], k0, k1);
                    mma16816(s[2*ng+1], qh[ks], k2, k3);
                }
            }

            // ---- mask (straddling tiles only) ----
            const int r0 = wr0 + (lane >> 2), r1 = r0 + 8;
            if (kbase + 63 > wr0) {
                #pragma unroll
                for (int j = 0; j < 8; j++) {
                    int c = kbase + j * 8 + (lane & 3) * 2;
                    if (c > r0)     s[j][0] = -1e30f;
                    if (c + 1 > r0) s[j][1] = -1e30f;
                    if (c > r1)     s[j][2] = -1e30f;
                    if (c + 1 > r1) s[j][3] = -1e30f;
                }
            }

            // ---- online softmax ----
            float rm0 = -1e30f, rm1 = -1e30f;
            #pragma unroll
            for (int j = 0; j < 8; j++) {
                rm0 = fmaxf(rm0, fmaxf(s[j][0], s[j][1]));
                rm1 = fmaxf(rm1, fmaxf(s[j][2], s[j][3]));
            }
            rm0 = fmaxf(rm0, __shfl_xor_sync(0xffffffffu, rm0, 1));
            rm0 = fmaxf(rm0, __shfl_xor_sync(0xffffffffu, rm0, 2));
            rm1 = fmaxf(rm1, __shfl_xor_sync(0xffffffffu, rm1, 1));
            rm1 = fmaxf(rm1, __shfl_xor_sync(0xffffffffu, rm1, 2));
            float mn0 = fmaxf(m0, rm0), mn1 = fmaxf(m1, rm1);
            float cr0 = __expf(m0 - mn0), cr1 = __expf(m1 - mn1);
            m0 = mn0; m1 = mn1;
            float ps0 = 0.f, ps1 = 0.f;
            #pragma unroll
            for (int j = 0; j < 8; j++) {
                s[j][0] = __expf(s[j][0] - m0);
                s[j][1] = __expf(s[j][1] - m0);
                s[j][2] = __expf(s[j][2] - m1);
                s[j][3] = __expf(s[j][3] - m1);
                ps0 += s[j][0] + s[j][1];
                ps1 += s[j][2] + s[j][3];
            }
            ps0 += __shfl_xor_sync(0xffffffffu, ps0, 1);
            ps0 += __shfl_xor_sync(0xffffffffu, ps0, 2);
            ps1 += __shfl_xor_sync(0xffffffffu, ps1, 1);
            ps1 += __shfl_xor_sync(0xffffffffu, ps1, 2);
            l0 = l0 * cr0 + ps0;
            l1 = l1 * cr1 + ps1;
            #pragma unroll
            for (int g = 0; g < 8; g++) {
                o[g][0] *= cr0; o[g][1] *= cr0;
                o[g][2] *= cr1; o[g][3] *= cr1;
            }

            // ---- O += P V (1-pass) ----
            #pragma unroll
            for (int t = 0; t < 4; t++) {
                uint32_t ph[4];
                ph[0] = pack2h(s[2*t][0],   s[2*t][1]);
                ph[1] = pack2h(s[2*t][2],   s[2*t][3]);
                ph[2] = pack2h(s[2*t+1][0], s[2*t+1][1]);
                ph[3] = pack2h(s[2*t+1][2], s[2*t+1][3]);
                #pragma unroll
                for (int dg = 0; dg < 4; dg++) {
                    uint32_t a = st + kAPlane
                               + (t * 16 + (lane & 7) + ((lane >> 3) & 1) * 8) * kARS
                               + dg * 32 + (lane >> 4) * 16;
                    uint32_t v0, v1, v2, v3;
                    ldsm_x4_t(v0, v1, v2, v3, a);
                    mma16816(o[2*dg],   ph, v0, v1);
                    mma16816(o[2*dg+1], ph, v2, v3);
                }
            }
        }
    }

    // ---- epilogue: O/l -> fp16 hi plane ----
    const float inv0 = 1.f / l0, inv1 = 1.f / l1;
    const size_t tok0 = (size_t)(b * kT) + wr0 + (lane >> 2);
    #pragma unroll
    for (int g = 0; g < 8; g++) {
        int col = h * 64 + g * 8 + (lane & 3) * 2;
        *reinterpret_cast<uint32_t*>(g_ab_h + tok0 * kD + col)
            = pack2h(o[g][0] * inv0, o[g][1] * inv0);
        *reinterpret_cast<uint32_t*>(g_ab_h + (tok0 + 8) * kD + col)
            = pack2h(o[g][2] * inv1, o[g][3] * inv1);
    }
}

// ---------------- conversion kernels ----------------
__global__ void convert_x(const float* __restrict__ x)
{
    int i = blockIdx.x * 256 + threadIdx.x;
    float4 v = ((const float4*)x)[i];
    size_t o = (size_t)i * 4;
    *reinterpret_cast<uint32_t*>(g_xb_h + o)     = pack2h(v.x, v.y);
    *reinterpret_cast<uint32_t*>(g_xb_h + o + 2) = pack2h(v.z, v.w);
}

__device__ __forceinline__ void transpose_body(
    const float* __restrict__ src, __half* __restrict__ hi,
    __half* __restrict__ lo, int K, int N)
{
    __shared__ float tile[32][33];
    int bn = blockIdx.x * 32, bk = blockIdx.y * 32;
    int tx = threadIdx.x, ty = threadIdx.y;
    #pragma unroll
    for (int i = 0; i < 32; i += 8)
        tile[ty + i][tx] = src[(size_t)(bk + ty + i) * N + bn + tx];
    __syncthreads();
    #pragma unroll
    for (int i = 0; i < 32; i += 8) {
        float v = tile[tx][ty + i];
        __half hh = __float2half_rn(v);
        size_t o = (size_t)(bn + ty + i) * K + bk + tx;
        hi[o] = hh;
        if (lo) lo[o] = __float2half_rn(v - __half2float(hh));
    }
}

__global__ void transpose_qkvo(const float* Wq, const float* Wk, const float* Wv, const float* Wo)
{
    int z = blockIdx.z;
    const float* src = (z == 0) ? Wq : (z == 1) ? Wk : (z == 2) ? Wv : Wo;
    // lo plane only needed for Wo (proj is 2-pass); harmless to compute all
    transpose_body(src, g_w4t_h + (size_t)z * kD * kD, g_w4t_l + (size_t)z * kD * kD, kD, kD);
}

__global__ void transpose_w1(const float* W1e)
{
    int e = blockIdx.z;
    size_t off = (size_t)e * kD * kFF;
    transpose_body(W1e + off, g_w1t_h + off, nullptr, kD, kFF);
}

__global__ void transpose_w2(const float* W2e)
{
    int e = blockIdx.z;
    size_t off = (size_t)e * kFF * kD;
    transpose_body(W2e + off, g_w2t_h + off, nullptr, kFF, kD);
}

// ---------------- add + layernorm ----------------
__device__ __forceinline__ float block_sum_256(float v, float* red)
{
    int tid = threadIdx.x;
    #pragma unroll
    for (int o = 16; o; o >>= 1) v += __shfl_xor_sync(0xffffffffu, v, o);
    if ((tid & 31) == 0) red[tid >> 5] = v;
    __syncthreads();
    if (tid < 8) {
        float x = red[tid];
        #pragma unroll
        for (int o = 4; o; o >>= 1) x += __shfl_xor_sync(0xffu, x, o);
        if (tid == 0) red[0] = x;
    }
    __syncthreads();
    float r = red[0];
    __syncthreads();
    return r;
}

__device__ __forceinline__ void add_ln_body(
    const float* __restrict__ A, const float* __restrict__ Bb,
    const float* __restrict__ gw, const float* __restrict__ bw,
    float* __restrict__ out, __half* __restrict__ oh)
{
    __shared__ float red[8];
    int t = blockIdx.x, tid = threadIdx.x;
    float4 av = ((const float4*)(A  + (size_t)t * kD))[tid];
    float4 bv = ((const float4*)(Bb + (size_t)t * kD))[tid];
    float vx = av.x + bv.x, vy = av.y + bv.y, vz = av.z + bv.z, vw = av.w + bv.w;
    float ssum = block_sum_256(vx + vy + vz + vw, red);
    float mu = ssum * (1.0f / kD);
    float dx = vx - mu, dy = vy - mu, dz = vz - mu, dw = vw - mu;
    float sq = block_sum_256(dx*dx + dy*dy + dz*dz + dw*dw, red);
    float rstd = rsqrtf(sq * (1.0f / kD) + kEPS);
    float4 gv = ((const float4*)gw)[tid];
    float4 be = ((const float4*)bw)[tid];
    float ovv[4] = {dx*rstd*gv.x + be.x, dy*rstd*gv.y + be.y,
                    dz*rstd*gv.z + be.z, dw*rstd*gv.w + be.w};
    ((float4*)(out + (size_t)t * kD))[tid] = make_float4(ovv[0], ovv[1], ovv[2], ovv[3]);
    if (oh) {
        size_t o = (size_t)t * kD + tid * 4;
        *reinterpret_cast<uint32_t*>(oh + o)     = pack2h(ovv[0], ovv[1]);
        *reinterpret_cast<uint32_t*>(oh + o + 2) = pack2h(ovv[2], ovv[3]);
    }
}

__global__ void ln1_kernel(const float* __restrict__ x,
                           const float* __restrict__ g, const float* __restrict__ b)
{
    add_ln_body(x, g_proj, g, b, g_x1, g_x1b_h);
}

__global__ void ln2_kernel(const float* __restrict__ g, const float* __restrict__ b,
                           float* __restrict__ out)
{
    add_ln_body(g_x1, g_y, g, b, out, nullptr);
}

// ---------------- MoE gate (top-1 argmax) ----------------
__global__ void zero_cnt()
{
    if (threadIdx.x < kE) g_cnt[threadIdx.x] = 0;
}

__global__ void gate_kernel(const float* __restrict__ Wg, const float* __restrict__ bg)
{
    int t = blockIdx.x, tid = threadIdx.x;
    float a0 = 0.f, a1 = 0.f, a2 = 0.f, a3 = 0.f;
    const float* xr = g_x1 + (size_t)t * kD;
    for (int d = tid; d < kD; d += 128) {
        float xv = xr[d];
        float4 w = ((const float4*)Wg)[d];
        a0 = fmaf(xv, w.x, a0);
        a1 = fmaf(xv, w.y, a1);
        a2 = fmaf(xv, w.z, a2);
        a3 = fmaf(xv, w.w, a3);
    }
    __shared__ float rsm[4][128];
    rsm[0][tid] = a0; rsm[1][tid] = a1; rsm[2][tid] = a2; rsm[3][tid] = a3;
    __syncthreads();
    for (int s = 64; s > 0; s >>= 1) {
        if (tid < s) {
            #pragma unroll
            for (int e = 0; e < 4; e++) rsm[e][tid] += rsm[e][tid + s];
        }
        __syncthreads();
    }
    if (tid == 0) {
        float sc[4];
        #pragma unroll
        for (int e = 0; e < 4; e++) sc[e] = rsm[e][0] + bg[e];
        int best = 0; float bvv = sc[0];
        #pragma unroll
        for (int e = 1; e < 4; e++) {
            if (sc[e] > bvv) { bvv = sc[e]; best = e; }
        }
        int pos = atomicAdd(&g_cnt[best], 1);
        g_list[best * kNT + pos] = t;
    }
}

// ---------------- launch ----------------
extern "C" void kernel_launch(void* const* d_in, const int* in_sizes, int n_in,
                              void* d_out, int out_size)
{
    const float* x    = (const float*)d_in[0];
    const float* Wq   = (const float*)d_in[2];
    const float* bq   = (const float*)d_in[3];
    const float* Wk   = (const float*)d_in[4];
    const float* bk   = (const float*)d_in[5];
    const float* Wv   = (const float*)d_in[6];
    const float* bv   = (const float*)d_in[7];
    const float* Wo   = (const float*)d_in[8];
    const float* bo   = (const float*)d_in[9];
    const float* ln1g = (const float*)d_in[10];
    const float* ln1b = (const float*)d_in[11];
    const float* Wg   = (const float*)d_in[12];
    const float* bg   = (const float*)d_in[13];
    const float* W1e  = (const float*)d_in[14];
    const float* b1e  = (const float*)d_in[15];
    const float* W2e  = (const float*)d_in[16];
    const float* b2e  = (const float*)d_in[17];
    const float* ln2g = (const float*)d_in[18];
    const float* ln2b = (const float*)d_in[19];
    float* out = (float*)d_out;

    cudaFuncSetAttribute(attn_tc, cudaFuncAttributeMaxDynamicSharedMemorySize, ATTN_SMEM);
    cudaFuncSetAttribute(qkv_tc,  cudaFuncAttributeMaxDynamicSharedMemorySize, GEMM_SMEM);
    cudaFuncSetAttribute(proj_tc, cudaFuncAttributeMaxDynamicSharedMemorySize, GEMM_SMEM);
    cudaFuncSetAttribute(moe1_tc, cudaFuncAttributeMaxDynamicSharedMemorySize, GEMM_SMEM);
    cudaFuncSetAttribute(moe2_tc, cudaFuncAttributeMaxDynamicSharedMemorySize, GEMM_SMEM);

    // side stream for prep work that can overlap the main chain
    cudaStream_t side;
    cudaEvent_t evFork, evJoin1, evJoin2;
    cudaStreamCreateWithFlags(&side, cudaStreamNonBlocking);
    cudaEventCreateWithFlags(&evFork, cudaEventDisableTiming);
    cudaEventCreateWithFlags(&evJoin1, cudaEventDisableTiming);
    cudaEventCreateWithFlags(&evJoin2, cudaEventDisableTiming);

    cudaEventRecord(evFork, 0);
    cudaStreamWaitEvent(side, evFork, 0);
    convert_x<<<kNT * kD / 4 / 256, 256, 0, side>>>(x);
    cudaEventRecord(evJoin1, side);
    transpose_w1<<<dim3(kFF/32, kD/32, kE), dim3(32, 8), 0, side>>>(W1e);
    transpose_w2<<<dim3(kD/32, kFF/32, kE), dim3(32, 8), 0, side>>>(W2e);
    cudaEventRecord(evJoin2, side);

    // main chain: attention path
    transpose_qkvo<<<dim3(kD/32, kD/32, 4), dim3(32, 8)>>>(Wq, Wk, Wv, Wo);
    cudaStreamWaitEvent(0, evJoin1, 0);
    qkv_tc<<<dim3(kD/128, kNT/128, 3), 256, GEMM_SMEM>>>(bq, bk, bv);
    attn_tc<<<dim3(kT/128, kB*kH), 256, ATTN_SMEM>>>();
    proj_tc<<<dim3(kD/128, kNT/128), 256, GEMM_SMEM>>>(bo);
    ln1_kernel<<<kNT, 256>>>(x, ln1g, ln1b);

    // MoE path
    zero_cnt<<<1, 32>>>();
    gate_kernel<<<kNT, 128>>>(Wg, bg);
    cudaStreamWaitEvent(0, evJoin2, 0);
    moe1_tc<<<dim3(kFF/128, kNT/128, kE), 256, GEMM_SMEM>>>(b1e);
    moe2_tc<<<dim3(kD/128, kNT/128, kE), 256, GEMM_SMEM>>>(b2e);
    ln2_kernel<<<kNT, 256>>>(ln2g, ln2b, out);
}

// round 15
// speedup vs baseline: 1.6692x; 1.0496x over previous
#include <cuda_runtime.h>
#include <cuda_fp16.h>
#include <math.h>
#include <stdint.h>

// ---------------- problem constants ----------------
constexpr int kB  = 2;
constexpr int kT  = 2048;
constexpr int kD  = 1024;
constexpr int kH  = 16;
constexpr int kDH = 64;
constexpr int kFF = 4096;
constexpr int kE  = 4;
constexpr int kNT = kB * kT;           // 4096 tokens
constexpr float kEPS = 1e-5f;

// ---------------- scratch (device globals: allocation-free) ----------------
__device__ float g_proj[kNT * kD];
__device__ float g_x1[kNT * kD];
__device__ float g_y[kNT * kD];
__device__ int   g_cnt[kE];
__device__ int   g_list[kE * kNT];

// fp16 planes (hi-only everywhere except none now)
__device__ __half g_xb_h[kNT * kD];
__device__ __half g_qb_h[kNT * kD];
__device__ __half g_kb_h[kNT * kD];
__device__ __half g_vb_h[kNT * kD];
__device__ __half g_ab_h[kNT * kD];
__device__ __half g_x1b_h[kNT * kD];
__device__ __half g_hb_h[(size_t)kNT * kFF];

__device__ __half g_w4t_h[4 * kD * kD];                          // Wq,Wk,Wv,Wo [N][K]
__device__ __half g_w1t_h[(size_t)kE * kFF * kD];
__device__ __half g_w2t_h[(size_t)kE * kFF * kD];

// ==================== PTX helpers (base sm_103 features only) ====================
__device__ __forceinline__ uint32_t smem_u32(const void* p) {
    uint32_t a;
    asm("{ .reg .u64 t; cvta.to.shared.u64 t, %1; cvt.u32.u64 %0, t; }" : "=r"(a) : "l"(p));
    return a;
}

__device__ __forceinline__ void cp_async16(uint32_t s, const void* g, int sz) {
    asm volatile("cp.async.cg.shared.global [%0], [%1], 16, %2;"
                 :: "r"(s), "l"(g), "r"(sz) : "memory");
}
#define CP_COMMIT()  asm volatile("cp.async.commit_group;" ::: "memory")
#define CP_WAIT(n)   asm volatile("cp.async.wait_group %0;" :: "n"(n) : "memory")

__device__ __forceinline__ void ldsm_x4(uint32_t& r0, uint32_t& r1, uint32_t& r2,
                                        uint32_t& r3, uint32_t addr) {
    asm volatile("ldmatrix.sync.aligned.m8n8.x4.shared.b16 {%0,%1,%2,%3}, [%4];"
                 : "=r"(r0), "=r"(r1), "=r"(r2), "=r"(r3) : "r"(addr));
}
__device__ __forceinline__ void ldsm_x4_t(uint32_t& r0, uint32_t& r1, uint32_t& r2,
                                          uint32_t& r3, uint32_t addr) {
    asm volatile("ldmatrix.sync.aligned.m8n8.x4.trans.shared.b16 {%0,%1,%2,%3}, [%4];"
                 : "=r"(r0), "=r"(r1), "=r"(r2), "=r"(r3) : "r"(addr));
}

__device__ __forceinline__ void mma16816(float* d, const uint32_t* a,
                                         uint32_t b0, uint32_t b1) {
    asm volatile("mma.sync.aligned.m16n8k16.row.col.f32.f16.f16.f32 "
                 "{%0,%1,%2,%3}, {%4,%5,%6,%7}, {%8,%9}, {%0,%1,%2,%3};"
                 : "+f"(d[0]), "+f"(d[1]), "+f"(d[2]), "+f"(d[3])
                 : "r"(a[0]), "r"(a[1]), "r"(a[2]), "r"(a[3]), "r"(b0), "r"(b1));
}

__device__ __forceinline__ uint32_t pack2h(float f0, float f1) {
    __half2 hv = __floats2half2_rn(f0, f1);
    return *reinterpret_cast<uint32_t*>(&hv);
}

// ==================== mma.sync fp16 GEMM (1-pass, hi-only) ====================
// Block 128x128, 256 threads (8 warps, 4Mx2N), warp tile 32x64, K-chunk 32.
constexpr int kPlaneB = 128 * 64;              // 8192 B per plane
constexpr int kStageB = 2 * kPlaneB;           // Ah Bh = 16384
constexpr int GEMM_SMEM = 3 * kStageB;         // 49152

__device__ __forceinline__ uint32_t swz(int row, int cb) {
    return (uint32_t)(row * 64 + ((((cb >> 4) ^ ((row >> 1) & 3))) << 4));
}

struct GemmPtrs {
    const __half *aH0, *aH1;
    const __half *bH0, *bH1;
    int v0, v1, c8;
};

__device__ __forceinline__ void fill_stage(uint32_t sb, int k0, const GemmPtrs& P)
{
    int row = threadIdx.x >> 2;                 // 0..63
    int cb  = (threadIdx.x & 3) * 16;
    uint32_t o0 = swz(row, cb);
    uint32_t o1 = o0 + 64 * 64;
    int g = k0 + P.c8;
    cp_async16(sb + o0,           P.aH0 + g, P.v0 ? 16 : 0);
    cp_async16(sb + o1,           P.aH1 + g, P.v1 ? 16 : 0);
    cp_async16(sb + kPlaneB + o0, P.bH0 + g, 16);
    cp_async16(sb + kPlaneB + o1, P.bH1 + g, 16);
}

// mode 0: C = acc + bias (fp32)
// mode 1: relu(acc+bias) -> Chi
// mode 2: (acc+bias)*scale -> Chi
__device__ __forceinline__ void gemm_tc(
    const __half* __restrict__ Ah, const __half* __restrict__ Bh,
    const float* __restrict__ bias, int K, int count, const int* __restrict__ list,
    int mode, float* __restrict__ C, __half* __restrict__ Chi, int ldc, float scale)
{
    extern __shared__ char sm[];
    const int tid  = threadIdx.x;
    const int wid  = tid >> 5, lane = tid & 31;
    const int rowBase = blockIdx.y * 128;
    const int colBase = blockIdx.x * 128;
    if (rowBase >= count) return;

    GemmPtrs P;
    {
        int r0 = tid >> 2;
        int gr0 = rowBase + r0, gr1 = rowBase + r0 + 64;
        P.v0 = gr0 < count;
        P.v1 = gr1 < count;
        int rr0 = P.v0 ? (list ? list[gr0] : gr0) : 0;
        int rr1 = P.v1 ? (list ? list[gr1] : gr1) : 0;
        P.aH0 = Ah + (size_t)rr0 * K;
        P.aH1 = Ah + (size_t)rr1 * K;
        P.bH0 = Bh + (size_t)(colBase + r0) * K;
        P.bH1 = Bh + (size_t)(colBase + r0 + 64) * K;
        P.c8  = (tid & 3) * 8;
    }
    const uint32_t smb = smem_u32(sm);

    const int wM = (wid & 3) * 32;
    const int wN = (wid >> 2) * 64;

    float acc[2][8][4];
    #pragma unroll
    for (int i = 0; i < 2; i++)
        #pragma unroll
        for (int j = 0; j < 8; j++)
            #pragma unroll
            for (int d = 0; d < 4; d++) acc[i][j][d] = 0.f;

    const int aCol = (lane >> 4) * 16;
    const int bRow = (lane & 7) + ((lane >> 4) & 1) * 8;
    const int bCol = ((lane >> 3) & 1) * 16;
    uint32_t offA[2][2], offB[4][2];
    #pragma unroll
    for (int mi = 0; mi < 2; mi++)
        #pragma unroll
        for (int s = 0; s < 2; s++)
            offA[mi][s] = swz(wM + mi * 16 + (lane & 15), s * 32 + aCol);
    #pragma unroll
    for (int nj = 0; nj < 4; nj++)
        #pragma unroll
        for (int s = 0; s < 2; s++)
            offB[nj][s] = kPlaneB + swz(wN + nj * 16 + bRow, s * 32 + bCol);

    const int nc = K / 32;
    fill_stage(smb, 0, P);
    CP_COMMIT();
    fill_stage(smb + kStageB, 32, P);
    CP_COMMIT();

    int buf = 0;
    for (int c = 0; c < nc; c++) {
        if (c + 1 < nc) { CP_WAIT(1); } else { CP_WAIT(0); }
        __syncthreads();
        if (c + 2 < nc) {
            int nb = buf + 2; if (nb >= 3) nb -= 3;
            fill_stage(smb + nb * kStageB, (c + 2) * 32, P);
            CP_COMMIT();
        }

        uint32_t st = smb + buf * kStageB;
        #pragma unroll
        for (int s = 0; s < 2; s++) {
            uint32_t ah[2][4];
            #pragma unroll
            for (int mi = 0; mi < 2; mi++)
                ldsm_x4(ah[mi][0], ah[mi][1], ah[mi][2], ah[mi][3], st + offA[mi][s]);
            #pragma unroll
            for (int njp = 0; njp < 4; njp++) {
                uint32_t bh[4];
                ldsm_x4(bh[0], bh[1], bh[2], bh[3], st + offB[njp][s]);
                #pragma unroll
                for (int mi = 0; mi < 2; mi++) {
                    #pragma unroll
                    for (int half = 0; half < 2; half++)
                        mma16816(acc[mi][njp * 2 + half], ah[mi],
                                 bh[half * 2], bh[half * 2 + 1]);
                }
            }
        }
        buf = (buf < 2) ? buf + 1 : 0;
    }

    #pragma unroll
    for (int mi = 0; mi < 2; mi++) {
        #pragma unroll
        for (int dd = 0; dd < 2; dd++) {
            int lrow = rowBase + wM + mi * 16 + (lane >> 2) + dd * 8;
            if (lrow >= count) continue;
            int orow = list ? list[lrow] : lrow;
            #pragma unroll
            for (int nj = 0; nj < 8; nj++) {
                int n = colBase + wN + nj * 8 + (lane & 3) * 2;
                float v0 = acc[mi][nj][dd * 2 + 0] + bias[n];
                float v1 = acc[mi][nj][dd * 2 + 1] + bias[n + 1];
                if (mode == 0) {
                    *reinterpret_cast<float2*>(C + (size_t)orow * ldc + n)
                        = make_float2(v0, v1);
                } else {
                    if (mode == 1) { v0 = fmaxf(v0, 0.f); v1 = fmaxf(v1, 0.f); }
                    else           { v0 *= scale; v1 *= scale; }
                    *reinterpret_cast<uint32_t*>(Chi + (size_t)orow * ldc + n)
                        = pack2h(v0, v1);
                }
            }
        }
    }
}

// ---------------- GEMM wrappers ----------------
__global__ void __launch_bounds__(256, 2) qkv_tc(const float* bq, const float* bk, const float* bv)
{
    int z = blockIdx.z;
    const __half* bh = g_w4t_h + (size_t)z * kD * kD;
    __half* ch = (z == 0) ? g_qb_h : (z == 1) ? g_kb_h : g_vb_h;
    const float* bias = (z == 0) ? bq : (z == 1) ? bk : bv;
    float scale = (z == 0) ? 0.125f : 1.0f;
    gemm_tc(g_xb_h, bh, bias, kD, kNT, nullptr, 2, nullptr, ch, kD, scale);
}

__global__ void __launch_bounds__(256, 2) proj_tc(const float* bo)
{
    gemm_tc(g_ab_h, g_w4t_h + (size_t)3 * kD * kD,
            bo, kD, kNT, nullptr, 0, g_proj, nullptr, kD, 1.f);
}

__global__ void __launch_bounds__(256, 2) moe1_tc(const float* b1e)
{
    int e = blockIdx.z;
    int cnt = g_cnt[e];
    gemm_tc(g_x1b_h, g_w1t_h + (size_t)e * kFF * kD,
            b1e + (size_t)e * kFF, kD, cnt, g_list + e * kNT,
            1, nullptr, g_hb_h, kFF, 1.f);
}

__global__ void __launch_bounds__(256, 2) moe2_tc(const float* b2e)
{
    int e = blockIdx.z;
    int cnt = g_cnt[e];
    gemm_tc(g_hb_h, g_w2t_h + (size_t)e * kFF * kD,
            b2e + (size_t)e * kD, kFF, cnt, g_list + e * kNT,
            0, g_y, nullptr, kD, 1.f);
}

// ==================== HMMA flash attention (causal, 1-pass fp16) ====================
constexpr int kARS    = 144;                   // padded row bytes
constexpr int kAPlane = 64 * kARS;             // 9216
constexpr int kAStage = 2 * kAPlane;           // Kh Vh = 18432
constexpr int kQOff   = 2 * kAStage;
constexpr int ATTN_SMEM = 2 * kAStage + 128 * kARS;   // 55296

__device__ __forceinline__ void fill_kv(uint32_t dst, int b, int h, int kbase)
{
    const __half* srcs[2] = {g_kb_h, g_vb_h};
    #pragma unroll
    for (int i = 0; i < 4; i++) {
        int lin = threadIdx.x + 256 * i;
        int ch = lin & 7, row = (lin >> 3) & 63, pl = lin >> 9;
        const __half* src = srcs[pl]
            + ((size_t)(b * kT + kbase + row) * kD + h * 64 + ch * 8);
        cp_async16(dst + pl * kAPlane + row * kARS + ch * 16, src, 16);
    }
}

__global__ void __launch_bounds__(256) attn_tc()
{
    extern __shared__ char sa[];
    const uint32_t smb = smem_u32(sa);
    const int tid = threadIdx.x, wid = tid >> 5, lane = tid & 31;
    const int qt = gridDim.x - 1 - blockIdx.x;   // longest-first
    const int bh = blockIdx.y;
    const int b = bh >> 4, h = bh & 15;
    const int qb = qt * 128;
    const int wr0 = qb + wid * 16;

    #pragma unroll
    for (int i = 0; i < 4; i++) {
        int lin = tid + 256 * i;
        int ch = lin & 7, row = lin >> 3;
        const __half* src = g_qb_h
            + ((size_t)(b * kT + qb + row) * kD + h * 64 + ch * 8);
        cp_async16(smb + kQOff + row * kARS + ch * 16, src, 16);
    }
    CP_COMMIT();
    fill_kv(smb, b, h, 0);
    CP_COMMIT();
    CP_WAIT(0);
    __syncthreads();

    uint32_t qh[4][4];
    #pragma unroll
    for (int ks = 0; ks < 4; ks++) {
        uint32_t addr = smb + kQOff + (wid * 16 + (lane & 15)) * kARS
                      + ks * 32 + (lane >> 4) * 16;
        ldsm_x4(qh[ks][0], qh[ks][1], qh[ks][2], qh[ks][3], addr);
    }

    float m0 = -1e30f, m1 = -1e30f, l0 = 0.f, l1 = 0.f;
    float o[8][4];
    #pragma unroll
    for (int g = 0; g < 8; g++)
        #pragma unroll
        for (int d = 0; d < 4; d++) o[g][d] = 0.f;

    const int ktmax = 2 * qt + 2;
    for (int kt = 0; kt < ktmax; kt++) {
        CP_WAIT(0);
        __syncthreads();
        if (kt + 1 < ktmax) {
            fill_kv(smb + ((kt + 1) & 1) * kAStage, b, h, (kt + 1) * 64);
            CP_COMMIT();
        }

        const int kbase = kt * 64;
        if (kbase <= wr0 + 15) {
            const uint32_t st = smb + (kt & 1) * kAStage;

            float s[8][4];
            #pragma unroll
            for (int j = 0; j < 8; j++)
                #pragma unroll
                for (int d = 0; d < 4; d++) s[j][d] = 0.f;

            #pragma unroll
            for (int ks = 0; ks < 4; ks++) {
                #pragma unroll
                for (int ng = 0; ng < 4; ng++) {
                    uint32_t a = st + (ng * 16 + (lane & 7) + (lane >> 4) * 8) * kARS
                               + ks * 32 + ((lane >> 3) & 1) * 16;
                    uint32_t k0, k1, k2, k3;
                    ldsm_x4(k0, k1, k2, k3, a);
                    mma16816(s[2*ng],   qh[ks], k0, k1);
                    mma16816(s[2*ng+1], qh[ks], k2, k3);
                }
            }

            const int r0 = wr0 + (lane >> 2), r1 = r0 + 8;
            if (kbase + 63 > wr0) {
                #pragma unroll
                for (int j = 0; j < 8; j++) {
                    int c = kbase + j * 8 + (lane & 3) * 2;
                    if (c > r0)     s[j][0] = -1e30f;
                    if (c + 1 > r0) s[j][1] = -1e30f;
                    if (c > r1)     s[j][2] = -1e30f;
                    if (c + 1 > r1) s[j][3] = -1e30f;
                }
            }

            float rm0 = -1e30f, rm1 = -1e30f;
            #pragma unroll
            for (int j = 0; j < 8; j++) {
                rm0 = fmaxf(rm0, fmaxf(s[j][0], s[j][1]));
                rm1 = fmaxf(rm1, fmaxf(s[j][2], s[j][3]));
            }
            rm0 = fmaxf(rm0, __shfl_xor_sync(0xffffffffu, rm0, 1));
            rm0 = fmaxf(rm0, __shfl_xor_sync(0xffffffffu, rm0, 2));
            rm1 = fmaxf(rm1, __shfl_xor_sync(0xffffffffu, rm1, 1));
            rm1 = fmaxf(rm1, __shfl_xor_sync(0xffffffffu, rm1, 2));
            float mn0 = fmaxf(m0, rm0), mn1 = fmaxf(m1, rm1);
            float cr0 = __expf(m0 - mn0), cr1 = __expf(m1 - mn1);
            m0 = mn0; m1 = mn1;
            float ps0 = 0.f, ps1 = 0.f;
            #pragma unroll
            for (int j = 0; j < 8; j++) {
                s[j][0] = __expf(s[j][0] - m0);
                s[j][1] = __expf(s[j][1] - m0);
                s[j][2] = __expf(s[j][2] - m1);
                s[j][3] = __expf(s[j][3] - m1);
                ps0 += s[j][0] + s[j][1];
                ps1 += s[j][2] + s[j][3];
            }
            ps0 += __shfl_xor_sync(0xffffffffu, ps0, 1);
            ps0 += __shfl_xor_sync(0xffffffffu, ps0, 2);
            ps1 += __shfl_xor_sync(0xffffffffu, ps1, 1);
            ps1 += __shfl_xor_sync(0xffffffffu, ps1, 2);
            l0 = l0 * cr0 + ps0;
            l1 = l1 * cr1 + ps1;
            #pragma unroll
            for (int g = 0; g < 8; g++) {
                o[g][0] *= cr0; o[g][1] *= cr0;
                o[g][2] *= cr1; o[g][3] *= cr1;
            }

            #pragma unroll
            for (int t = 0; t < 4; t++) {
                uint32_t ph[4];
                ph[0] = pack2h(s[2*t][0],   s[2*t][1]);
                ph[1] = pack2h(s[2*t][2],   s[2*t][3]);
                ph[2] = pack2h(s[2*t+1][0], s[2*t+1][1]);
                ph[3] = pack2h(s[2*t+1][2], s[2*t+1][3]);
                #pragma unroll
                for (int dg = 0; dg < 4; dg++) {
                    uint32_t a = st + kAPlane
                               + (t * 16 + (lane & 7) + ((lane >> 3) & 1) * 8) * kARS
                               + dg * 32 + (lane >> 4) * 16;
                    uint32_t v0, v1, v2, v3;
                    ldsm_x4_t(v0, v1, v2, v3, a);
                    mma16816(o[2*dg],   ph, v0, v1);
                    mma16816(o[2*dg+1], ph, v2, v3);
                }
            }
        }
    }

    const float inv0 = 1.f / l0, inv1 = 1.f / l1;
    const size_t tok0 = (size_t)(b * kT) + wr0 + (lane >> 2);
    #pragma unroll
    for (int g = 0; g < 8; g++) {
        int col = h * 64 + g * 8 + (lane & 3) * 2;
        *reinterpret_cast<uint32_t*>(g_ab_h + tok0 * kD + col)
            = pack2h(o[g][0] * inv0, o[g][1] * inv0);
        *reinterpret_cast<uint32_t*>(g_ab_h + (tok0 + 8) * kD + col)
            = pack2h(o[g][2] * inv1, o[g][3] * inv1);
    }
}

// ---------------- conversion kernels ----------------
__global__ void convert_x(const float* __restrict__ x)
{
    int i = blockIdx.x * 256 + threadIdx.x;
    float4 v = ((const float4*)x)[i];
    size_t o = (size_t)i * 4;
    *reinterpret_cast<uint32_t*>(g_xb_h + o)     = pack2h(v.x, v.y);
    *reinterpret_cast<uint32_t*>(g_xb_h + o + 2) = pack2h(v.z, v.w);
}

__device__ __forceinline__ void transpose_body(
    const float* __restrict__ src, __half* __restrict__ hi, int K, int N)
{
    __shared__ float tile[32][33];
    int bn = blockIdx.x * 32, bk = blockIdx.y * 32;
    int tx = threadIdx.x, ty = threadIdx.y;
    #pragma unroll
    for (int i = 0; i < 32; i += 8)
        tile[ty + i][tx] = src[(size_t)(bk + ty + i) * N + bn + tx];
    __syncthreads();
    #pragma unroll
    for (int i = 0; i < 32; i += 8) {
        size_t o = (size_t)(bn + ty + i) * K + bk + tx;
        hi[o] = __float2half_rn(tile[tx][ty + i]);
    }
}

__global__ void transpose_qkvo(const float* Wq, const float* Wk, const float* Wv, const float* Wo)
{
    int z = blockIdx.z;
    const float* src = (z == 0) ? Wq : (z == 1) ? Wk : (z == 2) ? Wv : Wo;
    transpose_body(src, g_w4t_h + (size_t)z * kD * kD, kD, kD);
}

__global__ void transpose_w1(const float* W1e)
{
    int e = blockIdx.z;
    size_t off = (size_t)e * kD * kFF;
    transpose_body(W1e + off, g_w1t_h + off, kD, kFF);
}

__global__ void transpose_w2(const float* W2e)
{
    int e = blockIdx.z;
    size_t off = (size_t)e * kFF * kD;
    transpose_body(W2e + off, g_w2t_h + off, kFF, kD);
}

// ---------------- add + layernorm (+ fused gate for ln1) ----------------
__device__ __forceinline__ float block_sum_256(float v, float* red)
{
    int tid = threadIdx.x;
    #pragma unroll
    for (int o = 16; o; o >>= 1) v += __shfl_xor_sync(0xffffffffu, v, o);
    if ((tid & 31) == 0) red[tid >> 5] = v;
    __syncthreads();
    if (tid < 8) {
        float x = red[tid];
        #pragma unroll
        for (int o = 4; o; o >>= 1) x += __shfl_xor_sync(0xffu, x, o);
        if (tid == 0) red[0] = x;
    }
    __syncthreads();
    float r = red[0];
    __syncthreads();
    return r;
}

// ln1: x1 = LN(x + proj); also fp16 copy and fused top-1 gate
__global__ void ln1_kernel(const float* __restrict__ x,
                           const float* __restrict__ g, const float* __restrict__ b,
                           const float* __restrict__ Wg, const float* __restrict__ bg)
{
    __shared__ float red[8];
    __shared__ float gsm[4][8];
    int t = blockIdx.x, tid = threadIdx.x;
    float4 av = ((const float4*)(x      + (size_t)t * kD))[tid];
    float4 bv = ((const float4*)(g_proj + (size_t)t * kD))[tid];
    float vx = av.x + bv.x, vy = av.y + bv.y, vz = av.z + bv.z, vw = av.w + bv.w;
    float ssum = block_sum_256(vx + vy + vz + vw, red);
    float mu = ssum * (1.0f / kD);
    float dx = vx - mu, dy = vy - mu, dz = vz - mu, dw = vw - mu;
    float sq = block_sum_256(dx*dx + dy*dy + dz*dz + dw*dw, red);
    float rstd = rsqrtf(sq * (1.0f / kD) + kEPS);
    float4 gv = ((const float4*)g)[tid];
    float4 be = ((const float4*)b)[tid];
    float ovv[4] = {dx*rstd*gv.x + be.x, dy*rstd*gv.y + be.y,
                    dz*rstd*gv.z + be.z, dw*rstd*gv.w + be.w};
    ((float4*)(g_x1 + (size_t)t * kD))[tid] = make_float4(ovv[0], ovv[1], ovv[2], ovv[3]);
    size_t o = (size_t)t * kD + tid * 4;
    *reinterpret_cast<uint32_t*>(g_x1b_h + o)     = pack2h(ovv[0], ovv[1]);
    *reinterpret_cast<uint32_t*>(g_x1b_h + o + 2) = pack2h(ovv[2], ovv[3]);

    // fused gate: scores = x1 @ Wg  (Wg is [D][E], E=4 -> one float4 per d)
    float ga[4] = {0.f, 0.f, 0.f, 0.f};
    #pragma unroll
    for (int j = 0; j < 4; j++) {
        float4 w = ((const float4*)Wg)[tid * 4 + j];
        ga[0] = fmaf(ovv[j], w.x, ga[0]);
        ga[1] = fmaf(ovv[j], w.y, ga[1]);
        ga[2] = fmaf(ovv[j], w.z, ga[2]);
        ga[3] = fmaf(ovv[j], w.w, ga[3]);
    }
    #pragma unroll
    for (int e = 0; e < 4; e++) {
        #pragma unroll
        for (int of = 16; of; of >>= 1)
            ga[e] += __shfl_xor_sync(0xffffffffu, ga[e], of);
    }
    if ((tid & 31) == 0) {
        int w = tid >> 5;
        gsm[0][w] = ga[0]; gsm[1][w] = ga[1]; gsm[2][w] = ga[2]; gsm[3][w] = ga[3];
    }
    __syncthreads();
    if (tid == 0) {
        float sc[4];
        #pragma unroll
        for (int e = 0; e < 4; e++) {
            float s = bg[e];
            #pragma unroll
            for (int w = 0; w < 8; w++) s += gsm[e][w];
            sc[e] = s;
        }
        int best = 0; float bvv = sc[0];
        #pragma unroll
        for (int e = 1; e < 4; e++)
            if (sc[e] > bvv) { bvv = sc[e]; best = e; }
        int pos = atomicAdd(&g_cnt[best], 1);
        g_list[best * kNT + pos] = t;
    }
}

__global__ void ln2_kernel(const float* __restrict__ g, const float* __restrict__ b,
                           float* __restrict__ out)
{
    __shared__ float red[8];
    int t = blockIdx.x, tid = threadIdx.x;
    float4 av = ((const float4*)(g_x1 + (size_t)t * kD))[tid];
    float4 bv = ((const float4*)(g_y  + (size_t)t * kD))[tid];
    float vx = av.x + bv.x, vy = av.y + bv.y, vz = av.z + bv.z, vw = av.w + bv.w;
    float ssum = block_sum_256(vx + vy + vz + vw, red);
    float mu = ssum * (1.0f / kD);
    float dx = vx - mu, dy = vy - mu, dz = vz - mu, dw = vw - mu;
    float sq = block_sum_256(dx*dx + dy*dy + dz*dz + dw*dw, red);
    float rstd = rsqrtf(sq * (1.0f / kD) + kEPS);
    float4 gv = ((const float4*)g)[tid];
    float4 be = ((const float4*)b)[tid];
    ((float4*)(out + (size_t)t * kD))[tid] = make_float4(
        dx*rstd*gv.x + be.x, dy*rstd*gv.y + be.y,
        dz*rstd*gv.z + be.z, dw*rstd*gv.w + be.w);
}

__global__ void zero_cnt()
{
    if (threadIdx.x < kE) g_cnt[threadIdx.x] = 0;
}

// ---------------- launch ----------------
extern "C" void kernel_launch(void* const* d_in, const int* in_sizes, int n_in,
                              void* d_out, int out_size)
{
    const float* x    = (const float*)d_in[0];
    const float* Wq   = (const float*)d_in[2];
    const float* bq   = (const float*)d_in[3];
    const float* Wk   = (const float*)d_in[4];
    const float* bk   = (const float*)d_in[5];
    const float* Wv   = (const float*)d_in[6];
    const float* bv   = (const float*)d_in[7];
    const float* Wo   = (const float*)d_in[8];
    const float* bo   = (const float*)d_in[9];
    const float* ln1g = (const float*)d_in[10];
    const float* ln1b = (const float*)d_in[11];
    const float* Wg   = (const float*)d_in[12];
    const float* bg   = (const float*)d_in[13];
    const float* W1e  = (const float*)d_in[14];
    const float* b1e  = (const float*)d_in[15];
    const float* W2e  = (const float*)d_in[16];
    const float* b2e  = (const float*)d_in[17];
    const float* ln2g = (const float*)d_in[18];
    const float* ln2b = (const float*)d_in[19];
    float* out = (float*)d_out;

    cudaFuncSetAttribute(attn_tc, cudaFuncAttributeMaxDynamicSharedMemorySize, ATTN_SMEM);
    cudaFuncSetAttribute(qkv_tc,  cudaFuncAttributeMaxDynamicSharedMemorySize, GEMM_SMEM);
    cudaFuncSetAttribute(proj_tc, cudaFuncAttributeMaxDynamicSharedMemorySize, GEMM_SMEM);
    cudaFuncSetAttribute(moe1_tc, cudaFuncAttributeMaxDynamicSharedMemorySize, GEMM_SMEM);
    cudaFuncSetAttribute(moe2_tc, cudaFuncAttributeMaxDynamicSharedMemorySize, GEMM_SMEM);

    // side stream for prep work that can overlap the main chain
    cudaStream_t side;
    cudaEvent_t evFork, evJoin1, evJoin2;
    cudaStreamCreateWithFlags(&side, cudaStreamNonBlocking);
    cudaEventCreateWithFlags(&evFork, cudaEventDisableTiming);
    cudaEventCreateWithFlags(&evJoin1, cudaEventDisableTiming);
    cudaEventCreateWithFlags(&evJoin2, cudaEventDisableTiming);

    cudaEventRecord(evFork, 0);
    cudaStreamWaitEvent(side, evFork, 0);
    convert_x<<<kNT * kD / 4 / 256, 256, 0, side>>>(x);
    cudaEventRecord(evJoin1, side);
    transpose_w1<<<dim3(kFF/32, kD/32, kE), dim3(32, 8), 0, side>>>(W1e);
    transpose_w2<<<dim3(kD/32, kFF/32, kE), dim3(32, 8), 0, side>>>(W2e);
    cudaEventRecord(evJoin2, side);

    // main chain: attention path
    zero_cnt<<<1, 32>>>();
    transpose_qkvo<<<dim3(kD/32, kD/32, 4), dim3(32, 8)>>>(Wq, Wk, Wv, Wo);
    cudaStreamWaitEvent(0, evJoin1, 0);
    qkv_tc<<<dim3(kD/128, kNT/128, 3), 256, GEMM_SMEM>>>(bq, bk, bv);
    attn_tc<<<dim3(kT/128, kB*kH), 256, ATTN_SMEM>>>();
    proj_tc<<<dim3(kD/128, kNT/128), 256, GEMM_SMEM>>>(bo);
    ln1_kernel<<<kNT, 256>>>(x, ln1g, ln1b, Wg, bg);

    // MoE path
    cudaStreamWaitEvent(0, evJoin2, 0);
    moe1_tc<<<dim3(kFF/128, kNT/128, kE), 256, GEMM_SMEM>>>(b1e);
    moe2_tc<<<dim3(kD/128, kNT/128, kE), 256, GEMM_SMEM>>>(b2e);
    ln2_kernel<<<kNT, 256>>>(ln2g, ln2b, out);
}